// round 7
// baseline (speedup 1.0000x reference)
#include <cuda_runtime.h>

#define NB   8
#define RR   256
#define IND  64
#define OUTD 64
#define MD   32
#define KXN  64

typedef unsigned long long ull;

// ---------------- scratch (device globals; no allocations allowed) ----------
__device__ float g_XwR[NB*MD*RR*IND];     // [n][ky][h][i]  forward w-DFT (re)
__device__ float g_XwI[NB*MD*RR*IND];
__device__ float g_XmR[NB*MD*KXN*IND];    // [ky][kx][n][i] forward modes
__device__ float g_XmI[NB*MD*KXN*IND];
__device__ float g_OmR[NB*MD*KXN*OUTD];   // [n][ky][kx][o] mixed modes
__device__ float g_OmI[NB*MD*KXN*OUTD];
__device__ float g_Y1R[NB*RR*MD*OUTD];    // [n][h][ky][o]  after inverse h-DFT
__device__ float g_Y1I[NB*RR*MD*OUTD];
__device__ float4 g_tw4p[256];            // (c, c,  s,  s)
__device__ float4 g_tw4n[256];            // (c, c, -s, -s)

// ---------------- packed f32x2 helpers --------------------------------------
__device__ __forceinline__ void fma2(ull &d, ull a, ull b) {
    asm("fma.rn.f32x2 %0, %1, %2, %0;" : "+l"(d) : "l"(a), "l"(b));
}
__device__ __forceinline__ ull splat2(float x) {
    ull r; asm("mov.b64 %0, {%1, %1};" : "=l"(r) : "f"(x)); return r;
}
__device__ __forceinline__ ull neg2(ull a, ull negone) {
    ull r; asm("mul.rn.f32x2 %0, %1, %2;" : "=l"(r) : "l"(a), "l"(negone)); return r;
}
__device__ __forceinline__ ull mul2(ull a, ull b) {
    ull r; asm("mul.rn.f32x2 %0, %1, %2;" : "=l"(r) : "l"(a), "l"(b)); return r;
}
__device__ __forceinline__ ull add2(ull a, ull b) {
    ull r; asm("add.rn.f32x2 %0, %1, %2;" : "=l"(r) : "l"(a), "l"(b)); return r;
}
__device__ __forceinline__ ull sub2(ull a, ull b, ull negone) {   // a - b
    ull r; asm("fma.rn.f32x2 %0, %1, %2, %3;" : "=l"(r) : "l"(b), "l"(negone), "l"(a)); return r;
}
__device__ __forceinline__ float2 unpk(ull v) {
    float2 r; asm("mov.b64 {%0, %1}, %2;" : "=f"(r.x), "=f"(r.y) : "l"(v)); return r;
}

__global__ void k_init_tw() {
    int k = threadIdx.x;
    double a = 6.283185307179586476925286766559 * (double)k / 256.0;
    float c = (float)cos(a), s = (float)sin(a);
    g_tw4p[k] = make_float4(c, c,  s,  s);
    g_tw4n[k] = make_float4(c, c, -s, -s);
}

// ---------------- K1: forward DFT along w (radix-4 decimation in time) ------
__global__ __launch_bounds__(128) void k1_fwd_w(const float* __restrict__ x) {
    extern __shared__ __align__(16) float us[];   // u0|u2|d02|d13, each [64][64]
    __shared__ __align__(16) float4 twp[256], twn[256];
    const int t = threadIdx.x;
    twp[t] = g_tw4p[t]; twp[t+128] = g_tw4p[t+128];
    twn[t] = g_tw4n[t]; twn[t+128] = g_tw4n[t+128];
    const int b = blockIdx.x, n = b >> 8, h = b & 255;
    const float* xb = x + (size_t)(n*RR + h)*RR*IND;
    float* u0s = us; float* u2s = us + 4096; float* d2s = us + 8192; float* d3s = us + 12288;
#pragma unroll
    for (int it = 0; it < 32; it++) {
        int idx = t + 128*it;                    // idx = w0*64 + i
        float a0 = xb[idx], a1 = xb[idx + 4096], a2 = xb[idx + 8192], a3 = xb[idx + 12288];
        float s02 = a0 + a2, d02 = a0 - a2, s13 = a1 + a3, d13 = a1 - a3;
        u0s[idx] = s02 + s13; u2s[idx] = s02 - s13; d2s[idx] = d02; d3s[idx] = d13;
    }
    __syncthreads();

    const int i0 = (t & 15) * 4, ky0 = (t >> 4) * 4;
    ull aR0[2]={0,0}, aI0[2]={0,0}, aR2[2]={0,0}, aI2[2]={0,0};
    ull aR1[2]={0,0}, bI1[2]={0,0}, aR3[2]={0,0}, aI3[2]={0,0};
    int p0 = 0, p1 = 0, p2 = 0, p3 = 0;
    for (int w0 = 0; w0 < 64; w0++) {
        const int off = w0*64 + i0;
        ulonglong2 U0 = *reinterpret_cast<const ulonglong2*>(&u0s[off]);
        ulonglong2 U2 = *reinterpret_cast<const ulonglong2*>(&u2s[off]);
        ulonglong2 D2 = *reinterpret_cast<const ulonglong2*>(&d2s[off]);
        ulonglong2 D3 = *reinterpret_cast<const ulonglong2*>(&d3s[off]);
        ulonglong2 tn4 = *reinterpret_cast<const ulonglong2*>(&twn[p0]);
        fma2(aR0[0], tn4.x, U0.x); fma2(aR0[1], tn4.x, U0.y);
        fma2(aI0[0], tn4.y, U0.x); fma2(aI0[1], tn4.y, U0.y);
        p0 = (p0 + ky0) & 255;
        ulonglong2 tp4 = *reinterpret_cast<const ulonglong2*>(&twp[p1]);
        tn4 = *reinterpret_cast<const ulonglong2*>(&twn[p1]);
        fma2(aR1[0], tp4.x, D2.x); fma2(aR1[1], tp4.x, D2.y);
        fma2(aR1[0], tn4.y, D3.x); fma2(aR1[1], tn4.y, D3.y);
        fma2(bI1[0], tp4.x, D3.x); fma2(bI1[1], tp4.x, D3.y);
        fma2(bI1[0], tp4.y, D2.x); fma2(bI1[1], tp4.y, D2.y);
        p1 = (p1 + ky0 + 1) & 255;
        tn4 = *reinterpret_cast<const ulonglong2*>(&twn[p2]);
        fma2(aR2[0], tn4.x, U2.x); fma2(aR2[1], tn4.x, U2.y);
        fma2(aI2[0], tn4.y, U2.x); fma2(aI2[1], tn4.y, U2.y);
        p2 = (p2 + ky0 + 2) & 255;
        tp4 = *reinterpret_cast<const ulonglong2*>(&twp[p3]);
        tn4 = *reinterpret_cast<const ulonglong2*>(&twn[p3]);
        fma2(aR3[0], tp4.x, D2.x); fma2(aR3[1], tp4.x, D2.y);
        fma2(aR3[0], tp4.y, D3.x); fma2(aR3[1], tp4.y, D3.y);
        fma2(aI3[0], tp4.x, D3.x); fma2(aI3[1], tp4.x, D3.y);
        fma2(aI3[0], tn4.y, D2.x); fma2(aI3[1], tn4.y, D2.y);
        p3 = (p3 + ky0 + 3) & 255;
    }
    const float sc = 1.f/256.f;
    ull* Rs[4] = {aR0, aR1, aR2, aR3};
    ull* Is[4] = {aI0, bI1, aI2, aI3};
    const float isc[4] = {sc, -sc, sc, sc};
#pragma unroll
    for (int k = 0; k < 4; k++) {
        size_t o = (size_t)((n*MD + ky0 + k)*RR + h)*IND + i0;
        float2 a0 = unpk(Rs[k][0]), a1 = unpk(Rs[k][1]);
        *reinterpret_cast<float4*>(&g_XwR[o]) = make_float4(a0.x*sc, a0.y*sc, a1.x*sc, a1.y*sc);
        a0 = unpk(Is[k][0]); a1 = unpk(Is[k][1]);
        float f = isc[k];
        *reinterpret_cast<float4*>(&g_XwI[o]) = make_float4(a0.x*f, a0.y*f, a1.x*f, a1.y*f);
    }
}

// ---------------- K2: forward h-DFT, radix-4 decimation in time -------------
// block=(n,ky,half). 32-h0 chunks (64KB dyn smem, 2 chunks -> 4 barriers).
__global__ __launch_bounds__(256) void k2_fwd_h() {
    extern __shared__ __align__(16) float Vs[];       // 8 planes x [32 h0][64 i]
    __shared__ __align__(16) float4 twp[256], twn[256];
    const int t = threadIdx.x;
    twp[t] = g_tw4p[t]; twn[t] = g_tw4n[t];
    const int b = blockIdx.x, half = b & 1, ky = (b >> 1) & 31, n = b >> 6;
    const float* baseR = g_XwR + (size_t)(n*MD + ky)*RR*IND;
    const float* baseI = g_XwI + (size_t)(n*MD + ky)*RR*IND;
    const int i0 = (t & 15) * 4;
    const int g = t >> 4, c = g & 3, mseg = g >> 2;
    const int kxl0 = 8*mseg + c;                       // slots of class c
    const int kap0 = half ? (224 + kxl0) : kxl0;
    const int kap1 = kap0 + 4;
    const ull NEG1 = splat2(-1.f);
    ull aR[2][2] = {{0,0},{0,0}}, aI[2][2] = {{0,0},{0,0}};
    int p0 = 0, p1 = 0;

    for (int hc = 0; hc < 64; hc += 32) {
        __syncthreads();
#pragma unroll
        for (int rr = 0; rr < 2; rr++) {               // 512 loader roles
            const int role = t + 256*rr;
            const int h0ld = role >> 4, iq = (role & 15) * 4;
            const float* pR = baseR + (hc + h0ld)*IND + iq;
            const float* pI = baseI + (hc + h0ld)*IND + iq;
            ulonglong2 R0 = *reinterpret_cast<const ulonglong2*>(pR);
            ulonglong2 R1 = *reinterpret_cast<const ulonglong2*>(pR + 64*IND);
            ulonglong2 R2 = *reinterpret_cast<const ulonglong2*>(pR + 128*IND);
            ulonglong2 R3 = *reinterpret_cast<const ulonglong2*>(pR + 192*IND);
            ulonglong2 I0 = *reinterpret_cast<const ulonglong2*>(pI);
            ulonglong2 I1 = *reinterpret_cast<const ulonglong2*>(pI + 64*IND);
            ulonglong2 I2 = *reinterpret_cast<const ulonglong2*>(pI + 128*IND);
            ulonglong2 I3 = *reinterpret_cast<const ulonglong2*>(pI + 192*IND);
            ull sRx = add2(R0.x, R2.x), sRy = add2(R0.y, R2.y);
            ull dRx = sub2(R0.x, R2.x, NEG1), dRy = sub2(R0.y, R2.y, NEG1);
            ull uRx = add2(R1.x, R3.x), uRy = add2(R1.y, R3.y);
            ull eRx = sub2(R1.x, R3.x, NEG1), eRy = sub2(R1.y, R3.y, NEG1);
            ull sIx = add2(I0.x, I2.x), sIy = add2(I0.y, I2.y);
            ull dIx = sub2(I0.x, I2.x, NEG1), dIy = sub2(I0.y, I2.y, NEG1);
            ull uIx = add2(I1.x, I3.x), uIy = add2(I1.y, I3.y);
            ull eIx = sub2(I1.x, I3.x, NEG1), eIy = sub2(I1.y, I3.y, NEG1);
            const int rb = h0ld*64 + iq;
            ulonglong2* vp;
            vp = reinterpret_cast<ulonglong2*>(&Vs[0*2048 + rb]);   // V0R
            *vp = make_ulonglong2(add2(sRx, uRx), add2(sRy, uRy));
            vp = reinterpret_cast<ulonglong2*>(&Vs[1*2048 + rb]);   // V0I
            *vp = make_ulonglong2(add2(sIx, uIx), add2(sIy, uIy));
            vp = reinterpret_cast<ulonglong2*>(&Vs[2*2048 + rb]);   // V1R = dR + eI
            *vp = make_ulonglong2(add2(dRx, eIx), add2(dRy, eIy));
            vp = reinterpret_cast<ulonglong2*>(&Vs[3*2048 + rb]);   // V1I = dI - eR
            *vp = make_ulonglong2(sub2(dIx, eRx, NEG1), sub2(dIy, eRy, NEG1));
            vp = reinterpret_cast<ulonglong2*>(&Vs[4*2048 + rb]);   // V2R
            *vp = make_ulonglong2(sub2(sRx, uRx, NEG1), sub2(sRy, uRy, NEG1));
            vp = reinterpret_cast<ulonglong2*>(&Vs[5*2048 + rb]);   // V2I
            *vp = make_ulonglong2(sub2(sIx, uIx, NEG1), sub2(sIy, uIy, NEG1));
            vp = reinterpret_cast<ulonglong2*>(&Vs[6*2048 + rb]);   // V3R = dR - eI
            *vp = make_ulonglong2(sub2(dRx, eIx, NEG1), sub2(dRy, eIy, NEG1));
            vp = reinterpret_cast<ulonglong2*>(&Vs[7*2048 + rb]);   // V3I = dI + eR
            *vp = make_ulonglong2(add2(dIx, eRx), add2(dIy, eRy));
        }
        __syncthreads();
        const float* VRb = &Vs[(c*2 + 0)*2048];
        const float* VIb = &Vs[(c*2 + 1)*2048];
        for (int h0l = 0; h0l < 32; h0l++) {
            ulonglong2 VR = *reinterpret_cast<const ulonglong2*>(&VRb[h0l*64 + i0]);
            ulonglong2 VI = *reinterpret_cast<const ulonglong2*>(&VIb[h0l*64 + i0]);
            // e^{-i th}: R' += c*VR + s*VI ; I' += c*VI - s*VR
            ulonglong2 tp4 = *reinterpret_cast<const ulonglong2*>(&twp[p0]);
            ulonglong2 tn4 = *reinterpret_cast<const ulonglong2*>(&twn[p0]);
            fma2(aR[0][0], tp4.x, VR.x); fma2(aR[0][0], tp4.y, VI.x);
            fma2(aR[0][1], tp4.x, VR.y); fma2(aR[0][1], tp4.y, VI.y);
            fma2(aI[0][0], tp4.x, VI.x); fma2(aI[0][0], tn4.y, VR.x);
            fma2(aI[0][1], tp4.x, VI.y); fma2(aI[0][1], tn4.y, VR.y);
            p0 = (p0 + kap0) & 255;
            tp4 = *reinterpret_cast<const ulonglong2*>(&twp[p1]);
            tn4 = *reinterpret_cast<const ulonglong2*>(&twn[p1]);
            fma2(aR[1][0], tp4.x, VR.x); fma2(aR[1][0], tp4.y, VI.x);
            fma2(aR[1][1], tp4.x, VR.y); fma2(aR[1][1], tp4.y, VI.y);
            fma2(aI[1][0], tp4.x, VI.x); fma2(aI[1][0], tn4.y, VR.x);
            fma2(aI[1][1], tp4.x, VI.y); fma2(aI[1][1], tn4.y, VR.y);
            p1 = (p1 + kap1) & 255;
        }
    }
#pragma unroll
    for (int j = 0; j < 2; j++) {
        int kxs = half*32 + kxl0 + 4*j;
        size_t o = (size_t)((ky*KXN + kxs)*NB + n)*IND + i0;
        float2 a0 = unpk(aR[j][0]), a1 = unpk(aR[j][1]);
        *reinterpret_cast<float4*>(&g_XmR[o]) = make_float4(a0.x, a0.y, a1.x, a1.y);
        a0 = unpk(aI[j][0]); a1 = unpk(aI[j][1]);
        *reinterpret_cast<float4*>(&g_XmI[o]) = make_float4(a0.x, a0.y, a1.x, a1.y);
    }
}

// ---------------- K3: per-mode complex channel mix (8x64x64) ----------------
__global__ __launch_bounds__(256) void k3_mix(const float* __restrict__ w0,
                                              const float* __restrict__ w1) {
    __shared__ float XsR[NB*IND], XsI[NB*IND];
    const int t = threadIdx.x, b = blockIdx.x;
    const int kx = b >> 5, ky = b & 31;
    size_t xb = (size_t)(ky*KXN + kx)*NB*IND;
    XsR[t] = g_XmR[xb + t]; XsR[t + 256] = g_XmR[xb + t + 256];
    XsI[t] = g_XmI[xb + t]; XsI[t + 256] = g_XmI[xb + t + 256];
    __syncthreads();
    const float2* wp = reinterpret_cast<const float2*>(
        (kx < MD) ? (w0 + (size_t)(kx*MD + ky)*IND*OUTD*2)
                  : (w1 + (size_t)((kx - MD)*MD + ky)*IND*OUTD*2));
    const int o = t & 63, n0 = t >> 6;
    float r0 = 0.f, i0 = 0.f, r1 = 0.f, i1 = 0.f;
#pragma unroll 8
    for (int i = 0; i < IND; i++) {
        float2 wv = wp[i*OUTD + o];
        float xr = XsR[n0*IND + i], xi = XsI[n0*IND + i];
        r0 = fmaf(xr, wv.x, fmaf(-xi, wv.y, r0));
        i0 = fmaf(xr, wv.y, fmaf( xi, wv.x, i0));
        xr = XsR[(n0+4)*IND + i]; xi = XsI[(n0+4)*IND + i];
        r1 = fmaf(xr, wv.x, fmaf(-xi, wv.y, r1));
        i1 = fmaf(xr, wv.y, fmaf( xi, wv.x, i1));
    }
    size_t g0 = (size_t)((n0*MD + ky)*KXN + kx)*OUTD + o;
    g_OmR[g0] = r0; g_OmI[g0] = i0;
    size_t g1 = (size_t)(((n0+4)*MD + ky)*KXN + kx)*OUTD + o;
    g_OmR[g1] = r1; g_OmI[g1] = i1;
}

// ---------------- K4: inverse h-DFT, radix-4 on output ----------------------
// block=(n,ky,grp of 32 h0), 256 thr: o0=(t&7)*8, h0=grp*32 + (t>>3).
// Streams output per j (no float4 staging) to cut register pressure.
#define K4STEP(CR, CI) { \
    ulonglong2 R0 = *reinterpret_cast<const ulonglong2*>(&sR[kxo]); \
    ulonglong2 R1 = *reinterpret_cast<const ulonglong2*>(&sR[kxo + 4]); \
    ulonglong2 I0 = *reinterpret_cast<const ulonglong2*>(&sI[kxo]); \
    ulonglong2 I1 = *reinterpret_cast<const ulonglong2*>(&sI[kxo + 4]); \
    ulonglong2 tp4 = *reinterpret_cast<const ulonglong2*>(&twp[p]); \
    ulonglong2 tn4 = *reinterpret_cast<const ulonglong2*>(&twn[p]); \
    fma2(CR[0], tn4.x, R0.x); fma2(CR[0], tn4.y, I0.x); \
    fma2(CR[1], tn4.x, R0.y); fma2(CR[1], tn4.y, I0.y); \
    fma2(CR[2], tn4.x, R1.x); fma2(CR[2], tn4.y, I1.x); \
    fma2(CR[3], tn4.x, R1.y); fma2(CR[3], tn4.y, I1.y); \
    fma2(CI[0], tp4.x, I0.x); fma2(CI[0], tp4.y, R0.x); \
    fma2(CI[1], tp4.x, I0.y); fma2(CI[1], tp4.y, R0.y); \
    fma2(CI[2], tp4.x, I1.x); fma2(CI[2], tp4.y, R1.x); \
    fma2(CI[3], tp4.x, I1.y); fma2(CI[3], tp4.y, R1.y); \
    p = (p + h0) & 255; kxo += OUTD; }

__global__ __launch_bounds__(256) void k4_inv_h() {
    __shared__ __align__(16) float sR[KXN*OUTD], sI[KXN*OUTD];
    __shared__ __align__(16) float4 twp[256], twn[256];
    const int t = threadIdx.x;
    twp[t] = g_tw4p[t]; twn[t] = g_tw4n[t];
    const int b = blockIdx.x, grp = b & 1, ky = (b >> 1) & 31, n = b >> 6;
    const float4* pR = reinterpret_cast<const float4*>(g_OmR + (size_t)(n*MD + ky)*KXN*OUTD);
    const float4* pI = reinterpret_cast<const float4*>(g_OmI + (size_t)(n*MD + ky)*KXN*OUTD);
#pragma unroll
    for (int it = 0; it < 4; it++) {
        reinterpret_cast<float4*>(sR)[t + 256*it] = pR[t + 256*it];
        reinterpret_cast<float4*>(sI)[t + 256*it] = pI[t + 256*it];
    }
    __syncthreads();
    const int o0 = (t & 7) * 8, h0 = grp*32 + (t >> 3);
    ull C0R[4], C0I[4], C1R[4], C1I[4], C2R[4], C2I[4], C3R[4], C3I[4];
#pragma unroll
    for (int j = 0; j < 4; j++) {
        C0R[j]=C0I[j]=C1R[j]=C1I[j]=0ull;
        C2R[j]=C2I[j]=C3R[j]=C3I[j]=0ull;
    }
#pragma unroll 1
    for (int kh = 0; kh < 2; kh++) {
        int p = kh ? ((224*h0) & 255) : 0;
        int kxo = (kh*32)*OUTD + o0;
#pragma unroll
        for (int kk = 0; kk < 32; kk += 4) {
            K4STEP(C0R, C0I)
            K4STEP(C1R, C1I)
            K4STEP(C2R, C2I)
            K4STEP(C3R, C3I)
        }
    }
    const ull NEG1 = splat2(-1.f);
    const ull FAC2 = splat2((ky == 0 ? 1.f : 2.f) * (1.f/256.f));
    const size_t obase = (size_t)((n*RR + h0)*MD + ky)*OUTD + o0;
#pragma unroll
    for (int j = 0; j < 4; j++) {
        ull ER = add2(C0R[j], C2R[j]), EI = add2(C0I[j], C2I[j]);
        ull FR = sub2(C0R[j], C2R[j], NEG1), FI = sub2(C0I[j], C2I[j], NEG1);
        ull GR = add2(C1R[j], C3R[j]), GI = add2(C1I[j], C3I[j]);
        ull HR = sub2(C1R[j], C3R[j], NEG1), HI = sub2(C1I[j], C3I[j], NEG1);
        ull YR[4] = { add2(ER, GR), sub2(FR, HI, NEG1), sub2(ER, GR, NEG1), add2(FR, HI) };
        ull YI[4] = { add2(EI, GI), add2(FI, HR), sub2(EI, GI, NEG1), sub2(FI, HR, NEG1) };
#pragma unroll
        for (int q = 0; q < 4; q++) {
            size_t o = obase + (size_t)(64*q)*MD*OUTD + 2*j;
            *reinterpret_cast<float2*>(&g_Y1R[o]) = unpk(mul2(YR[q], FAC2));
            *reinterpret_cast<float2*>(&g_Y1I[o]) = unpk(mul2(YI[q], FAC2));
        }
    }
}

// ---------------- K5: radix-4 inverse w synthesis + residual + SiLU ---------
// block=(n,h), 256 thr: og = t&7 (8 o), pr = t>>3 -> w0a = pr, w0b = pr+32.
#define XPAD 68
__global__ __launch_bounds__(256) void k5_inv_w(const float* __restrict__ x,
                                                const float* __restrict__ res_w,
                                                const float* __restrict__ res_b,
                                                float* __restrict__ out) {
    extern __shared__ __align__(16) float xs[];       // [256][XPAD]
    __shared__ __align__(16) float YsR[MD*OUTD], YsI[MD*OUTD];
    __shared__ __align__(16) float rws[IND*OUTD];
    __shared__ __align__(16) float4 twp[256], twn[256];
    __shared__ __align__(16) float rbs[64];
    const int t = threadIdx.x, b = blockIdx.x, n = b >> 8, h = b & 255;
    twp[t] = g_tw4p[t];
    twn[t] = g_tw4n[t];
    const float4* xp = reinterpret_cast<const float4*>(x + (size_t)(n*RR + h)*RR*IND);
#pragma unroll
    for (int it = 0; it < 16; it++) {
        int j = t + 256*it;
        float4 v = xp[j];
        int w = j >> 4, c = j & 15;
        *reinterpret_cast<float4*>(&xs[w*XPAD + c*4]) = v;
    }
    const float4* yR4 = reinterpret_cast<const float4*>(g_Y1R + (size_t)(n*RR + h)*MD*OUTD);
    const float4* yI4 = reinterpret_cast<const float4*>(g_Y1I + (size_t)(n*RR + h)*MD*OUTD);
#pragma unroll
    for (int it = 0; it < 2; it++) {
        reinterpret_cast<float4*>(YsR)[t + 256*it] = yR4[t + 256*it];
        reinterpret_cast<float4*>(YsI)[t + 256*it] = yI4[t + 256*it];
    }
#pragma unroll
    for (int it = 0; it < 4; it++)
        reinterpret_cast<float4*>(rws)[t + 256*it] =
            reinterpret_cast<const float4*>(res_w)[t + 256*it];
    if (t < 64) rbs[t] = res_b[t];
    __syncthreads();

    const int og = t & 7, o0 = og*8, pr = t >> 3;     // w0a = pr, w0b = pr + 32
    const ull NEG1 = splat2(-1.f);
    // class accumulators: [s][o-pair], s=0 -> w0a, s=1 -> w0b
    ull C0R[2][4], C2R[2][4], C1R[2][4], C1I[2][4], C3R[2][4], C3I[2][4];
#pragma unroll
    for (int s = 0; s < 2; s++)
#pragma unroll
        for (int j = 0; j < 4; j++) {
            C0R[s][j]=C2R[s][j]=C1R[s][j]=C1I[s][j]=C3R[s][j]=C3I[s][j]=0ull;
        }
    int pa = 0, pb = 0;
    const int stpa = pr, stpb = pr + 32;
#pragma unroll
    for (int kb = 0; kb < 8; kb++) {
        // c = 0
        {
            const int ky = 4*kb;
            ulonglong2 yr0 = *reinterpret_cast<const ulonglong2*>(&YsR[ky*OUTD + o0]);
            ulonglong2 yr1 = *reinterpret_cast<const ulonglong2*>(&YsR[ky*OUTD + o0 + 4]);
            ulonglong2 yi0 = *reinterpret_cast<const ulonglong2*>(&YsI[ky*OUTD + o0]);
            ulonglong2 yi1 = *reinterpret_cast<const ulonglong2*>(&YsI[ky*OUTD + o0 + 4]);
            ulonglong2 tn4 = *reinterpret_cast<const ulonglong2*>(&twn[pa]);
            fma2(C0R[0][0], tn4.x, yr0.x); fma2(C0R[0][0], tn4.y, yi0.x);
            fma2(C0R[0][1], tn4.x, yr0.y); fma2(C0R[0][1], tn4.y, yi0.y);
            fma2(C0R[0][2], tn4.x, yr1.x); fma2(C0R[0][2], tn4.y, yi1.x);
            fma2(C0R[0][3], tn4.x, yr1.y); fma2(C0R[0][3], tn4.y, yi1.y);
            tn4 = *reinterpret_cast<const ulonglong2*>(&twn[pb]);
            fma2(C0R[1][0], tn4.x, yr0.x); fma2(C0R[1][0], tn4.y, yi0.x);
            fma2(C0R[1][1], tn4.x, yr0.y); fma2(C0R[1][1], tn4.y, yi0.y);
            fma2(C0R[1][2], tn4.x, yr1.x); fma2(C0R[1][2], tn4.y, yi1.x);
            fma2(C0R[1][3], tn4.x, yr1.y); fma2(C0R[1][3], tn4.y, yi1.y);
            pa = (pa + stpa) & 255; pb = (pb + stpb) & 255;
        }
        // c = 1
        {
            const int ky = 4*kb + 1;
            ulonglong2 yr0 = *reinterpret_cast<const ulonglong2*>(&YsR[ky*OUTD + o0]);
            ulonglong2 yr1 = *reinterpret_cast<const ulonglong2*>(&YsR[ky*OUTD + o0 + 4]);
            ulonglong2 yi0 = *reinterpret_cast<const ulonglong2*>(&YsI[ky*OUTD + o0]);
            ulonglong2 yi1 = *reinterpret_cast<const ulonglong2*>(&YsI[ky*OUTD + o0 + 4]);
            ulonglong2 tn4 = *reinterpret_cast<const ulonglong2*>(&twn[pa]);
            ulonglong2 tp4 = *reinterpret_cast<const ulonglong2*>(&twp[pa]);
            fma2(C1R[0][0], tn4.x, yr0.x); fma2(C1R[0][0], tn4.y, yi0.x);
            fma2(C1R[0][1], tn4.x, yr0.y); fma2(C1R[0][1], tn4.y, yi0.y);
            fma2(C1R[0][2], tn4.x, yr1.x); fma2(C1R[0][2], tn4.y, yi1.x);
            fma2(C1R[0][3], tn4.x, yr1.y); fma2(C1R[0][3], tn4.y, yi1.y);
            fma2(C1I[0][0], tp4.x, yi0.x); fma2(C1I[0][0], tp4.y, yr0.x);
            fma2(C1I[0][1], tp4.x, yi0.y); fma2(C1I[0][1], tp4.y, yr0.y);
            fma2(C1I[0][2], tp4.x, yi1.x); fma2(C1I[0][2], tp4.y, yr1.x);
            fma2(C1I[0][3], tp4.x, yi1.y); fma2(C1I[0][3], tp4.y, yr1.y);
            tn4 = *reinterpret_cast<const ulonglong2*>(&twn[pb]);
            tp4 = *reinterpret_cast<const ulonglong2*>(&twp[pb]);
            fma2(C1R[1][0], tn4.x, yr0.x); fma2(C1R[1][0], tn4.y, yi0.x);
            fma2(C1R[1][1], tn4.x, yr0.y); fma2(C1R[1][1], tn4.y, yi0.y);
            fma2(C1R[1][2], tn4.x, yr1.x); fma2(C1R[1][2], tn4.y, yi1.x);
            fma2(C1R[1][3], tn4.x, yr1.y); fma2(C1R[1][3], tn4.y, yi1.y);
            fma2(C1I[1][0], tp4.x, yi0.x); fma2(C1I[1][0], tp4.y, yr0.x);
            fma2(C1I[1][1], tp4.x, yi0.y); fma2(C1I[1][1], tp4.y, yr0.y);
            fma2(C1I[1][2], tp4.x, yi1.x); fma2(C1I[1][2], tp4.y, yr1.x);
            fma2(C1I[1][3], tp4.x, yi1.y); fma2(C1I[1][3], tp4.y, yr1.y);
            pa = (pa + stpa) & 255; pb = (pb + stpb) & 255;
        }
        // c = 2
        {
            const int ky = 4*kb + 2;
            ulonglong2 yr0 = *reinterpret_cast<const ulonglong2*>(&YsR[ky*OUTD + o0]);
            ulonglong2 yr1 = *reinterpret_cast<const ulonglong2*>(&YsR[ky*OUTD + o0 + 4]);
            ulonglong2 yi0 = *reinterpret_cast<const ulonglong2*>(&YsI[ky*OUTD + o0]);
            ulonglong2 yi1 = *reinterpret_cast<const ulonglong2*>(&YsI[ky*OUTD + o0 + 4]);
            ulonglong2 tn4 = *reinterpret_cast<const ulonglong2*>(&twn[pa]);
            fma2(C2R[0][0], tn4.x, yr0.x); fma2(C2R[0][0], tn4.y, yi0.x);
            fma2(C2R[0][1], tn4.x, yr0.y); fma2(C2R[0][1], tn4.y, yi0.y);
            fma2(C2R[0][2], tn4.x, yr1.x); fma2(C2R[0][2], tn4.y, yi1.x);
            fma2(C2R[0][3], tn4.x, yr1.y); fma2(C2R[0][3], tn4.y, yi1.y);
            tn4 = *reinterpret_cast<const ulonglong2*>(&twn[pb]);
            fma2(C2R[1][0], tn4.x, yr0.x); fma2(C2R[1][0], tn4.y, yi0.x);
            fma2(C2R[1][1], tn4.x, yr0.y); fma2(C2R[1][1], tn4.y, yi0.y);
            fma2(C2R[1][2], tn4.x, yr1.x); fma2(C2R[1][2], tn4.y, yi1.x);
            fma2(C2R[1][3], tn4.x, yr1.y); fma2(C2R[1][3], tn4.y, yi1.y);
            pa = (pa + stpa) & 255; pb = (pb + stpb) & 255;
        }
        // c = 3
        {
            const int ky = 4*kb + 3;
            ulonglong2 yr0 = *reinterpret_cast<const ulonglong2*>(&YsR[ky*OUTD + o0]);
            ulonglong2 yr1 = *reinterpret_cast<const ulonglong2*>(&YsR[ky*OUTD + o0 + 4]);
            ulonglong2 yi0 = *reinterpret_cast<const ulonglong2*>(&YsI[ky*OUTD + o0]);
            ulonglong2 yi1 = *reinterpret_cast<const ulonglong2*>(&YsI[ky*OUTD + o0 + 4]);
            ulonglong2 tn4 = *reinterpret_cast<const ulonglong2*>(&twn[pa]);
            ulonglong2 tp4 = *reinterpret_cast<const ulonglong2*>(&twp[pa]);
            fma2(C3R[0][0], tn4.x, yr0.x); fma2(C3R[0][0], tn4.y, yi0.x);
            fma2(C3R[0][1], tn4.x, yr0.y); fma2(C3R[0][1], tn4.y, yi0.y);
            fma2(C3R[0][2], tn4.x, yr1.x); fma2(C3R[0][2], tn4.y, yi1.x);
            fma2(C3R[0][3], tn4.x, yr1.y); fma2(C3R[0][3], tn4.y, yi1.y);
            fma2(C3I[0][0], tp4.x, yi0.x); fma2(C3I[0][0], tp4.y, yr0.x);
            fma2(C3I[0][1], tp4.x, yi0.y); fma2(C3I[0][1], tp4.y, yr0.y);
            fma2(C3I[0][2], tp4.x, yi1.x); fma2(C3I[0][2], tp4.y, yr1.x);
            fma2(C3I[0][3], tp4.x, yi1.y); fma2(C3I[0][3], tp4.y, yr1.y);
            tn4 = *reinterpret_cast<const ulonglong2*>(&twn[pb]);
            tp4 = *reinterpret_cast<const ulonglong2*>(&twp[pb]);
            fma2(C3R[1][0], tn4.x, yr0.x); fma2(C3R[1][0], tn4.y, yi0.x);
            fma2(C3R[1][1], tn4.x, yr0.y); fma2(C3R[1][1], tn4.y, yi0.y);
            fma2(C3R[1][2], tn4.x, yr1.x); fma2(C3R[1][2], tn4.y, yi1.x);
            fma2(C3R[1][3], tn4.x, yr1.y); fma2(C3R[1][3], tn4.y, yi1.y);
            fma2(C3I[1][0], tp4.x, yi0.x); fma2(C3I[1][0], tp4.y, yr0.x);
            fma2(C3I[1][1], tp4.x, yi0.y); fma2(C3I[1][1], tp4.y, yr0.y);
            fma2(C3I[1][2], tp4.x, yi1.x); fma2(C3I[1][2], tp4.y, yr1.x);
            fma2(C3I[1][3], tp4.x, yi1.y); fma2(C3I[1][3], tp4.y, yr1.y);
            pa = (pa + stpa) & 255; pb = (pb + stpb) & 255;
        }
    }
    // ---- combine classes into 4 output rows + bias, both w0 ----
    ull ys[2][4][4];
    {
        ulonglong2 b01 = *reinterpret_cast<const ulonglong2*>(&rbs[o0]);
        ulonglong2 b23 = *reinterpret_cast<const ulonglong2*>(&rbs[o0 + 4]);
        ull bias[4] = {b01.x, b01.y, b23.x, b23.y};
#pragma unroll
        for (int s = 0; s < 2; s++)
#pragma unroll
            for (int j = 0; j < 4; j++) {
                ull e  = add2(C0R[s][j], C2R[s][j]);
                ull f  = sub2(C0R[s][j], C2R[s][j], NEG1);
                ull g  = add2(C1R[s][j], C3R[s][j]);
                ull hh = sub2(C3I[s][j], C1I[s][j], NEG1);
                ys[s][0][j] = add2(add2(e, g),  bias[j]);
                ys[s][2][j] = add2(sub2(e, g,  NEG1), bias[j]);
                ys[s][1][j] = add2(add2(f, hh), bias[j]);
                ys[s][3][j] = add2(sub2(f, hh, NEG1), bias[j]);
            }
    }
    // ---- residual GEMM into ys ----
    for (int i = 0; i < IND; i++) {
        ulonglong2 r01 = *reinterpret_cast<const ulonglong2*>(&rws[i*OUTD + o0]);
        ulonglong2 r23 = *reinterpret_cast<const ulonglong2*>(&rws[i*OUTD + o0 + 4]);
#pragma unroll
        for (int s = 0; s < 2; s++) {
            const int wbase = pr + 32*s;
#pragma unroll
            for (int q = 0; q < 4; q++) {
                ull sx = splat2(xs[(wbase + 64*q)*XPAD + i]);
                fma2(ys[s][q][0], sx, r01.x); fma2(ys[s][q][1], sx, r01.y);
                fma2(ys[s][q][2], sx, r23.x); fma2(ys[s][q][3], sx, r23.y);
            }
        }
    }
    // ---- SiLU + store ----
#pragma unroll
    for (int s = 0; s < 2; s++) {
        const int wbase = pr + 32*s;
#pragma unroll
        for (int q = 0; q < 4; q++) {
            float4 v4[2];
#pragma unroll
            for (int c = 0; c < 4; c++) {
                float2 v = unpk(ys[s][q][c]);
                v.x = v.x / (1.f + __expf(-v.x));
                v.y = v.y / (1.f + __expf(-v.y));
                reinterpret_cast<float2*>(v4)[c] = v;
            }
            size_t o = (size_t)((n*RR + h)*RR + (wbase + 64*q))*OUTD + o0;
            *reinterpret_cast<float4*>(&out[o])     = v4[0];
            *reinterpret_cast<float4*>(&out[o + 4]) = v4[1];
        }
    }
}

// ---------------- launch ----------------------------------------------------
extern "C" void kernel_launch(void* const* d_in, const int* in_sizes, int n_in,
                              void* d_out, int out_size) {
    const float* x   = (const float*)d_in[0];
    const float* w0  = (const float*)d_in[1];
    const float* w1  = (const float*)d_in[2];
    const float* rsw = (const float*)d_in[3];
    const float* rsb = (const float*)d_in[4];
    float* out = (float*)d_out;

    cudaFuncSetAttribute(k1_fwd_w, cudaFuncAttributeMaxDynamicSharedMemorySize, 65536);
    cudaFuncSetAttribute(k2_fwd_h, cudaFuncAttributeMaxDynamicSharedMemorySize, 65536);
    cudaFuncSetAttribute(k5_inv_w, cudaFuncAttributeMaxDynamicSharedMemorySize, RR*XPAD*4);

    k_init_tw<<<1, 256>>>();
    k1_fwd_w<<<NB*RR, 128, 65536>>>(x);
    k2_fwd_h<<<NB*MD*2, 256, 65536>>>();
    k3_mix<<<KXN*MD, 256>>>(w0, w1);
    k4_inv_h<<<NB*MD*2, 256>>>();
    k5_inv_w<<<NB*RR, 256, RR*XPAD*4>>>(x, rsw, rsb, out);
}

// round 10
// speedup vs baseline: 1.0444x; 1.0444x over previous
#include <cuda_runtime.h>

#define NB   8
#define RR   256
#define IND  64
#define OUTD 64
#define MD   32
#define KXN  64

typedef unsigned long long ull;

// ---------------- scratch (device globals; no allocations allowed) ----------
__device__ float g_XwR[NB*MD*RR*IND];     // [n][ky][h][i]  forward w-DFT (re)
__device__ float g_XwI[NB*MD*RR*IND];
__device__ float g_XmR[NB*MD*KXN*IND];    // [ky][kx][n][i] forward modes
__device__ float g_XmI[NB*MD*KXN*IND];
__device__ float g_OmR[NB*MD*KXN*OUTD];   // [n][ky][kx][o] mixed modes
__device__ float g_OmI[NB*MD*KXN*OUTD];
__device__ float g_Y1R[NB*RR*MD*OUTD];    // [n][h][ky][o]  after inverse h-DFT
__device__ float g_Y1I[NB*RR*MD*OUTD];
__device__ float4 g_tw4p[256];            // (c, c,  s,  s)
__device__ float4 g_tw4n[256];            // (c, c, -s, -s)

// ---------------- packed f32x2 helpers --------------------------------------
__device__ __forceinline__ void fma2(ull &d, ull a, ull b) {
    asm("fma.rn.f32x2 %0, %1, %2, %0;" : "+l"(d) : "l"(a), "l"(b));
}
__device__ __forceinline__ ull splat2(float x) {
    ull r; asm("mov.b64 %0, {%1, %1};" : "=l"(r) : "f"(x)); return r;
}
__device__ __forceinline__ ull neg2(ull a, ull negone) {
    ull r; asm("mul.rn.f32x2 %0, %1, %2;" : "=l"(r) : "l"(a), "l"(negone)); return r;
}
__device__ __forceinline__ ull mul2(ull a, ull b) {
    ull r; asm("mul.rn.f32x2 %0, %1, %2;" : "=l"(r) : "l"(a), "l"(b)); return r;
}
__device__ __forceinline__ ull add2(ull a, ull b) {
    ull r; asm("add.rn.f32x2 %0, %1, %2;" : "=l"(r) : "l"(a), "l"(b)); return r;
}
__device__ __forceinline__ ull sub2(ull a, ull b, ull negone) {   // a - b
    ull r; asm("fma.rn.f32x2 %0, %1, %2, %3;" : "=l"(r) : "l"(b), "l"(negone), "l"(a)); return r;
}
__device__ __forceinline__ float2 unpk(ull v) {
    float2 r; asm("mov.b64 {%0, %1}, %2;" : "=f"(r.x), "=f"(r.y) : "l"(v)); return r;
}

__global__ void k_init_tw() {
    int k = threadIdx.x;
    double a = 6.283185307179586476925286766559 * (double)k / 256.0;
    float c = (float)cos(a), s = (float)sin(a);
    g_tw4p[k] = make_float4(c, c,  s,  s);
    g_tw4n[k] = make_float4(c, c, -s, -s);
}

// ---------------- K1: forward DFT along w (radix-4, 256 thr, 2 ky/thread) ---
// warps 0-3: even ky classes (u0/u2); warps 4-7: odd classes (d02/d13).
// Each thread handles ky_a and ky_b = ky_a + 16 (same class mod 4).
__global__ __launch_bounds__(256) void k1_fwd_w(const float* __restrict__ x) {
    extern __shared__ __align__(16) float us[];   // u0|u2|d02|d13, each [64][64]
    __shared__ __align__(16) float4 twp[256], twn[256];
    const int t = threadIdx.x;
    twp[t] = g_tw4p[t]; twn[t] = g_tw4n[t];
    const int b = blockIdx.x, n = b >> 8, h = b & 255;
    const float* xb = x + (size_t)(n*RR + h)*RR*IND;
    float* u0s = us; float* u2s = us + 4096; float* d2s = us + 8192; float* d3s = us + 12288;
#pragma unroll
    for (int it = 0; it < 16; it++) {
        int idx = t + 256*it;                    // idx = w0*64 + i
        float a0 = xb[idx], a1 = xb[idx + 4096], a2 = xb[idx + 8192], a3 = xb[idx + 12288];
        float s02 = a0 + a2, d02 = a0 - a2, s13 = a1 + a3, d13 = a1 - a3;
        u0s[idx] = s02 + s13; u2s[idx] = s02 - s13; d2s[idx] = d02; d3s[idx] = d13;
    }
    __syncthreads();

    const int i0 = (t & 15) * 4;
    const int slot = (t >> 4) & 7;
    const bool oddky = (t >= 128);               // warp-uniform
    const int ky_a = 2*slot + (oddky ? 1 : 0);
    const int ky_b = ky_a + 16;
    ull aR[2][2] = {{0,0},{0,0}}, aI[2][2] = {{0,0},{0,0}};
    int pa = 0, pb = 0;
    const float sc = 1.f/256.f;
    float iscl = sc;

    if (!oddky) {
        // class 0 (slot even) uses u0; class 2 (slot odd) uses u2
        const float* Up = (slot & 1) ? u2s : u0s;
        for (int w0 = 0; w0 < 64; w0++) {
            ulonglong2 U = *reinterpret_cast<const ulonglong2*>(&Up[w0*64 + i0]);
            ulonglong2 ta = *reinterpret_cast<const ulonglong2*>(&twn[pa]);
            fma2(aR[0][0], ta.x, U.x); fma2(aR[0][1], ta.x, U.y);
            fma2(aI[0][0], ta.y, U.x); fma2(aI[0][1], ta.y, U.y);
            ulonglong2 tb = *reinterpret_cast<const ulonglong2*>(&twn[pb]);
            fma2(aR[1][0], tb.x, U.x); fma2(aR[1][1], tb.x, U.y);
            fma2(aI[1][0], tb.y, U.x); fma2(aI[1][1], tb.y, U.y);
            pa = (pa + ky_a) & 255; pb = (pb + ky_b) & 255;
        }
    } else {
        // class 1 (slot even): R = c*D2 - s*D3 ; Ipre = c*D3 + s*D2 (store -sc)
        // class 3 (slot odd):  R = c*D2 + s*D3 ; I    = c*D3 - s*D2 (store +sc)
        const bool c1 = ((slot & 1) == 0);
        const ull S = splat2(c1 ? 1.f : -1.f);
        iscl = c1 ? -sc : sc;
        for (int w0 = 0; w0 < 64; w0++) {
            ulonglong2 D2 = *reinterpret_cast<const ulonglong2*>(&d2s[w0*64 + i0]);
            ulonglong2 D3 = *reinterpret_cast<const ulonglong2*>(&d3s[w0*64 + i0]);
            ull D3r0 = mul2(D3.x, S), D3r1 = mul2(D3.y, S);
            ull D2i0 = mul2(D2.x, S), D2i1 = mul2(D2.y, S);
            ulonglong2 tpa = *reinterpret_cast<const ulonglong2*>(&twp[pa]);
            ulonglong2 tna = *reinterpret_cast<const ulonglong2*>(&twn[pa]);
            fma2(aR[0][0], tpa.x, D2.x); fma2(aR[0][1], tpa.x, D2.y);
            fma2(aR[0][0], tna.y, D3r0); fma2(aR[0][1], tna.y, D3r1);
            fma2(aI[0][0], tpa.x, D3.x); fma2(aI[0][1], tpa.x, D3.y);
            fma2(aI[0][0], tpa.y, D2i0); fma2(aI[0][1], tpa.y, D2i1);
            ulonglong2 tpb = *reinterpret_cast<const ulonglong2*>(&twp[pb]);
            ulonglong2 tnb = *reinterpret_cast<const ulonglong2*>(&twn[pb]);
            fma2(aR[1][0], tpb.x, D2.x); fma2(aR[1][1], tpb.x, D2.y);
            fma2(aR[1][0], tnb.y, D3r0); fma2(aR[1][1], tnb.y, D3r1);
            fma2(aI[1][0], tpb.x, D3.x); fma2(aI[1][1], tpb.x, D3.y);
            fma2(aI[1][0], tpb.y, D2i0); fma2(aI[1][1], tpb.y, D2i1);
            pa = (pa + ky_a) & 255; pb = (pb + ky_b) & 255;
        }
    }
#pragma unroll
    for (int j = 0; j < 2; j++) {
        const int ky = j ? ky_b : ky_a;
        size_t o = (size_t)((n*MD + ky)*RR + h)*IND + i0;
        float2 a0 = unpk(aR[j][0]), a1 = unpk(aR[j][1]);
        *reinterpret_cast<float4*>(&g_XwR[o]) = make_float4(a0.x*sc, a0.y*sc, a1.x*sc, a1.y*sc);
        a0 = unpk(aI[j][0]); a1 = unpk(aI[j][1]);
        *reinterpret_cast<float4*>(&g_XwI[o]) = make_float4(a0.x*iscl, a0.y*iscl, a1.x*iscl, a1.y*iscl);
    }
}

// ---------------- K2: forward h-DFT, radix-4, register-prefetch pipeline ----
// block=(n,ky,half). 16-h0 chunks; next chunk's raw rows prefetched into regs
// while contracting the current chunk, butterflied from regs into Vs.
__global__ __launch_bounds__(256, 3) void k2_fwd_h() {
    __shared__ __align__(16) float Vs[8*16*64];       // 8 planes x [16 h0][64 i] = 32KB
    __shared__ __align__(16) float4 twp[256], twn[256];
    const int t = threadIdx.x;
    twp[t] = g_tw4p[t]; twn[t] = g_tw4n[t];
    const int b = blockIdx.x, half = b & 1, ky = (b >> 1) & 31, n = b >> 6;
    const float* baseR = g_XwR + (size_t)(n*MD + ky)*RR*IND;
    const float* baseI = g_XwI + (size_t)(n*MD + ky)*RR*IND;
    const int i0 = (t & 15) * 4;
    const int g = t >> 4, c = g & 3, mseg = g >> 2;
    const int kxl0 = 8*mseg + c;                       // slots of class c
    const int kap0 = half ? (224 + kxl0) : kxl0;
    const int kap1 = kap0 + 4;
    const int h0ld = t >> 4, iq = (t & 15) * 4;        // loader role (1 per thread)
    const ull NEG1 = splat2(-1.f);
    ull aR[2][2] = {{0,0},{0,0}}, aI[2][2] = {{0,0},{0,0}};
    int p0 = 0, p1 = 0;

    // prefetch chunk 0 raw rows into registers
    ulonglong2 R0, R1, R2, R3, I0, I1, I2, I3;
    {
        const float* pR = baseR + h0ld*IND + iq;
        const float* pI = baseI + h0ld*IND + iq;
        R0 = *reinterpret_cast<const ulonglong2*>(pR);
        R1 = *reinterpret_cast<const ulonglong2*>(pR + 64*IND);
        R2 = *reinterpret_cast<const ulonglong2*>(pR + 128*IND);
        R3 = *reinterpret_cast<const ulonglong2*>(pR + 192*IND);
        I0 = *reinterpret_cast<const ulonglong2*>(pI);
        I1 = *reinterpret_cast<const ulonglong2*>(pI + 64*IND);
        I2 = *reinterpret_cast<const ulonglong2*>(pI + 128*IND);
        I3 = *reinterpret_cast<const ulonglong2*>(pI + 192*IND);
    }

    for (int hc = 0; hc < 64; hc += 16) {
        __syncthreads();                               // Vs free (prev chunk consumed)
        {   // butterfly registers -> Vs
            ull sRx = add2(R0.x, R2.x), sRy = add2(R0.y, R2.y);
            ull dRx = sub2(R0.x, R2.x, NEG1), dRy = sub2(R0.y, R2.y, NEG1);
            ull uRx = add2(R1.x, R3.x), uRy = add2(R1.y, R3.y);
            ull eRx = sub2(R1.x, R3.x, NEG1), eRy = sub2(R1.y, R3.y, NEG1);
            ull sIx = add2(I0.x, I2.x), sIy = add2(I0.y, I2.y);
            ull dIx = sub2(I0.x, I2.x, NEG1), dIy = sub2(I0.y, I2.y, NEG1);
            ull uIx = add2(I1.x, I3.x), uIy = add2(I1.y, I3.y);
            ull eIx = sub2(I1.x, I3.x, NEG1), eIy = sub2(I1.y, I3.y, NEG1);
            const int rb = h0ld*64 + iq;
            ulonglong2* vp;
            vp = reinterpret_cast<ulonglong2*>(&Vs[0*1024 + rb]);   // V0R
            *vp = make_ulonglong2(add2(sRx, uRx), add2(sRy, uRy));
            vp = reinterpret_cast<ulonglong2*>(&Vs[1*1024 + rb]);   // V0I
            *vp = make_ulonglong2(add2(sIx, uIx), add2(sIy, uIy));
            vp = reinterpret_cast<ulonglong2*>(&Vs[2*1024 + rb]);   // V1R = dR + eI
            *vp = make_ulonglong2(add2(dRx, eIx), add2(dRy, eIy));
            vp = reinterpret_cast<ulonglong2*>(&Vs[3*1024 + rb]);   // V1I = dI - eR
            *vp = make_ulonglong2(sub2(dIx, eRx, NEG1), sub2(dIy, eRy, NEG1));
            vp = reinterpret_cast<ulonglong2*>(&Vs[4*1024 + rb]);   // V2R
            *vp = make_ulonglong2(sub2(sRx, uRx, NEG1), sub2(sRy, uRy, NEG1));
            vp = reinterpret_cast<ulonglong2*>(&Vs[5*1024 + rb]);   // V2I
            *vp = make_ulonglong2(sub2(sIx, uIx, NEG1), sub2(sIy, uIy, NEG1));
            vp = reinterpret_cast<ulonglong2*>(&Vs[6*1024 + rb]);   // V3R = dR - eI
            *vp = make_ulonglong2(sub2(dRx, eIx, NEG1), sub2(dRy, eIy, NEG1));
            vp = reinterpret_cast<ulonglong2*>(&Vs[7*1024 + rb]);   // V3I = dI + eR
            *vp = make_ulonglong2(add2(dIx, eRx), add2(dIy, eRy));
        }
        __syncthreads();                               // Vs ready
        if (hc < 48) {                                 // prefetch next chunk (latency
            const float* pR = baseR + (hc + 16 + h0ld)*IND + iq;   //  hidden by contraction)
            const float* pI = baseI + (hc + 16 + h0ld)*IND + iq;
            R0 = *reinterpret_cast<const ulonglong2*>(pR);
            R1 = *reinterpret_cast<const ulonglong2*>(pR + 64*IND);
            R2 = *reinterpret_cast<const ulonglong2*>(pR + 128*IND);
            R3 = *reinterpret_cast<const ulonglong2*>(pR + 192*IND);
            I0 = *reinterpret_cast<const ulonglong2*>(pI);
            I1 = *reinterpret_cast<const ulonglong2*>(pI + 64*IND);
            I2 = *reinterpret_cast<const ulonglong2*>(pI + 128*IND);
            I3 = *reinterpret_cast<const ulonglong2*>(pI + 192*IND);
        }
        const float* VRb = &Vs[(c*2 + 0)*1024];
        const float* VIb = &Vs[(c*2 + 1)*1024];
        for (int h0l = 0; h0l < 16; h0l++) {
            ulonglong2 VR = *reinterpret_cast<const ulonglong2*>(&VRb[h0l*64 + i0]);
            ulonglong2 VI = *reinterpret_cast<const ulonglong2*>(&VIb[h0l*64 + i0]);
            // e^{-i th}: R' += c*VR + s*VI ; I' += c*VI - s*VR
            ulonglong2 tp4 = *reinterpret_cast<const ulonglong2*>(&twp[p0]);
            ulonglong2 tn4 = *reinterpret_cast<const ulonglong2*>(&twn[p0]);
            fma2(aR[0][0], tp4.x, VR.x); fma2(aR[0][0], tp4.y, VI.x);
            fma2(aR[0][1], tp4.x, VR.y); fma2(aR[0][1], tp4.y, VI.y);
            fma2(aI[0][0], tp4.x, VI.x); fma2(aI[0][0], tn4.y, VR.x);
            fma2(aI[0][1], tp4.x, VI.y); fma2(aI[0][1], tn4.y, VR.y);
            p0 = (p0 + kap0) & 255;
            tp4 = *reinterpret_cast<const ulonglong2*>(&twp[p1]);
            tn4 = *reinterpret_cast<const ulonglong2*>(&twn[p1]);
            fma2(aR[1][0], tp4.x, VR.x); fma2(aR[1][0], tp4.y, VI.x);
            fma2(aR[1][1], tp4.x, VR.y); fma2(aR[1][1], tp4.y, VI.y);
            fma2(aI[1][0], tp4.x, VI.x); fma2(aI[1][0], tn4.y, VR.x);
            fma2(aI[1][1], tp4.x, VI.y); fma2(aI[1][1], tn4.y, VR.y);
            p1 = (p1 + kap1) & 255;
        }
    }
#pragma unroll
    for (int j = 0; j < 2; j++) {
        int kxs = half*32 + kxl0 + 4*j;
        size_t o = (size_t)((ky*KXN + kxs)*NB + n)*IND + i0;
        float2 a0 = unpk(aR[j][0]), a1 = unpk(aR[j][1]);
        *reinterpret_cast<float4*>(&g_XmR[o]) = make_float4(a0.x, a0.y, a1.x, a1.y);
        a0 = unpk(aI[j][0]); a1 = unpk(aI[j][1]);
        *reinterpret_cast<float4*>(&g_XmI[o]) = make_float4(a0.x, a0.y, a1.x, a1.y);
    }
}

// ---------------- K3: per-mode complex channel mix (8x64x64) ----------------
__global__ __launch_bounds__(256) void k3_mix(const float* __restrict__ w0,
                                              const float* __restrict__ w1) {
    __shared__ float XsR[NB*IND], XsI[NB*IND];
    const int t = threadIdx.x, b = blockIdx.x;
    const int kx = b >> 5, ky = b & 31;
    size_t xb = (size_t)(ky*KXN + kx)*NB*IND;
    XsR[t] = g_XmR[xb + t]; XsR[t + 256] = g_XmR[xb + t + 256];
    XsI[t] = g_XmI[xb + t]; XsI[t + 256] = g_XmI[xb + t + 256];
    __syncthreads();
    const float2* wp = reinterpret_cast<const float2*>(
        (kx < MD) ? (w0 + (size_t)(kx*MD + ky)*IND*OUTD*2)
                  : (w1 + (size_t)((kx - MD)*MD + ky)*IND*OUTD*2));
    const int o = t & 63, n0 = t >> 6;
    float r0 = 0.f, i0 = 0.f, r1 = 0.f, i1 = 0.f;
#pragma unroll 8
    for (int i = 0; i < IND; i++) {
        float2 wv = wp[i*OUTD + o];
        float xr = XsR[n0*IND + i], xi = XsI[n0*IND + i];
        r0 = fmaf(xr, wv.x, fmaf(-xi, wv.y, r0));
        i0 = fmaf(xr, wv.y, fmaf( xi, wv.x, i0));
        xr = XsR[(n0+4)*IND + i]; xi = XsI[(n0+4)*IND + i];
        r1 = fmaf(xr, wv.x, fmaf(-xi, wv.y, r1));
        i1 = fmaf(xr, wv.y, fmaf( xi, wv.x, i1));
    }
    size_t g0 = (size_t)((n0*MD + ky)*KXN + kx)*OUTD + o;
    g_OmR[g0] = r0; g_OmI[g0] = i0;
    size_t g1 = (size_t)(((n0+4)*MD + ky)*KXN + kx)*OUTD + o;
    g_OmR[g1] = r1; g_OmI[g1] = i1;
}

// ---------------- K4: inverse h-DFT, radix-4 on output ----------------------
#define K4STEP(CR, CI) { \
    ulonglong2 R0 = *reinterpret_cast<const ulonglong2*>(&sR[kxo]); \
    ulonglong2 R1 = *reinterpret_cast<const ulonglong2*>(&sR[kxo + 4]); \
    ulonglong2 I0 = *reinterpret_cast<const ulonglong2*>(&sI[kxo]); \
    ulonglong2 I1 = *reinterpret_cast<const ulonglong2*>(&sI[kxo + 4]); \
    ulonglong2 tp4 = *reinterpret_cast<const ulonglong2*>(&twp[p]); \
    ulonglong2 tn4 = *reinterpret_cast<const ulonglong2*>(&twn[p]); \
    fma2(CR[0], tn4.x, R0.x); fma2(CR[0], tn4.y, I0.x); \
    fma2(CR[1], tn4.x, R0.y); fma2(CR[1], tn4.y, I0.y); \
    fma2(CR[2], tn4.x, R1.x); fma2(CR[2], tn4.y, I1.x); \
    fma2(CR[3], tn4.x, R1.y); fma2(CR[3], tn4.y, I1.y); \
    fma2(CI[0], tp4.x, I0.x); fma2(CI[0], tp4.y, R0.x); \
    fma2(CI[1], tp4.x, I0.y); fma2(CI[1], tp4.y, R0.y); \
    fma2(CI[2], tp4.x, I1.x); fma2(CI[2], tp4.y, R1.x); \
    fma2(CI[3], tp4.x, I1.y); fma2(CI[3], tp4.y, R1.y); \
    p = (p + h0) & 255; kxo += OUTD; }

__global__ __launch_bounds__(256) void k4_inv_h() {
    __shared__ __align__(16) float sR[KXN*OUTD], sI[KXN*OUTD];
    __shared__ __align__(16) float4 twp[256], twn[256];
    const int t = threadIdx.x;
    twp[t] = g_tw4p[t]; twn[t] = g_tw4n[t];
    const int b = blockIdx.x, grp = b & 1, ky = (b >> 1) & 31, n = b >> 6;
    const float4* pR = reinterpret_cast<const float4*>(g_OmR + (size_t)(n*MD + ky)*KXN*OUTD);
    const float4* pI = reinterpret_cast<const float4*>(g_OmI + (size_t)(n*MD + ky)*KXN*OUTD);
#pragma unroll
    for (int it = 0; it < 4; it++) {
        reinterpret_cast<float4*>(sR)[t + 256*it] = pR[t + 256*it];
        reinterpret_cast<float4*>(sI)[t + 256*it] = pI[t + 256*it];
    }
    __syncthreads();
    const int o0 = (t & 7) * 8, h0 = grp*32 + (t >> 3);
    ull C0R[4], C0I[4], C1R[4], C1I[4], C2R[4], C2I[4], C3R[4], C3I[4];
#pragma unroll
    for (int j = 0; j < 4; j++) {
        C0R[j]=C0I[j]=C1R[j]=C1I[j]=0ull;
        C2R[j]=C2I[j]=C3R[j]=C3I[j]=0ull;
    }
#pragma unroll 1
    for (int kh = 0; kh < 2; kh++) {
        int p = kh ? ((224*h0) & 255) : 0;
        int kxo = (kh*32)*OUTD + o0;
#pragma unroll
        for (int kk = 0; kk < 32; kk += 4) {
            K4STEP(C0R, C0I)
            K4STEP(C1R, C1I)
            K4STEP(C2R, C2I)
            K4STEP(C3R, C3I)
        }
    }
    const ull NEG1 = splat2(-1.f);
    const ull FAC2 = splat2((ky == 0 ? 1.f : 2.f) * (1.f/256.f));
    const size_t obase = (size_t)((n*RR + h0)*MD + ky)*OUTD + o0;
#pragma unroll
    for (int j = 0; j < 4; j++) {
        ull ER = add2(C0R[j], C2R[j]), EI = add2(C0I[j], C2I[j]);
        ull FR = sub2(C0R[j], C2R[j], NEG1), FI = sub2(C0I[j], C2I[j], NEG1);
        ull GR = add2(C1R[j], C3R[j]), GI = add2(C1I[j], C3I[j]);
        ull HR = sub2(C1R[j], C3R[j], NEG1), HI = sub2(C1I[j], C3I[j], NEG1);
        ull YR[4] = { add2(ER, GR), sub2(FR, HI, NEG1), sub2(ER, GR, NEG1), add2(FR, HI) };
        ull YI[4] = { add2(EI, GI), add2(FI, HR), sub2(EI, GI, NEG1), sub2(FI, HR, NEG1) };
#pragma unroll
        for (int q = 0; q < 4; q++) {
            size_t o = obase + (size_t)(64*q)*MD*OUTD + 2*j;
            *reinterpret_cast<float2*>(&g_Y1R[o]) = unpk(mul2(YR[q], FAC2));
            *reinterpret_cast<float2*>(&g_Y1I[o]) = unpk(mul2(YI[q], FAC2));
        }
    }
}

// ---------------- K5: radix-4 inverse w synthesis + residual + SiLU ---------
// block=(n,h), 256 thr: og = t&7 (8 o), pr = t>>3 -> w0a = pr, w0b = pr+32.
#define XPAD 68
__global__ __launch_bounds__(256) void k5_inv_w(const float* __restrict__ x,
                                                const float* __restrict__ res_w,
                                                const float* __restrict__ res_b,
                                                float* __restrict__ out) {
    extern __shared__ __align__(16) float xs[];       // [256][XPAD]
    __shared__ __align__(16) float YsR[MD*OUTD], YsI[MD*OUTD];
    __shared__ __align__(16) float rws[IND*OUTD];
    __shared__ __align__(16) float4 twp[256], twn[256];
    __shared__ __align__(16) float rbs[64];
    const int t = threadIdx.x, b = blockIdx.x, n = b >> 8, h = b & 255;
    twp[t] = g_tw4p[t];
    twn[t] = g_tw4n[t];
    const float4* xp = reinterpret_cast<const float4*>(x + (size_t)(n*RR + h)*RR*IND);
#pragma unroll
    for (int it = 0; it < 16; it++) {
        int j = t + 256*it;
        float4 v = xp[j];
        int w = j >> 4, c = j & 15;
        *reinterpret_cast<float4*>(&xs[w*XPAD + c*4]) = v;
    }
    const float4* yR4 = reinterpret_cast<const float4*>(g_Y1R + (size_t)(n*RR + h)*MD*OUTD);
    const float4* yI4 = reinterpret_cast<const float4*>(g_Y1I + (size_t)(n*RR + h)*MD*OUTD);
#pragma unroll
    for (int it = 0; it < 2; it++) {
        reinterpret_cast<float4*>(YsR)[t + 256*it] = yR4[t + 256*it];
        reinterpret_cast<float4*>(YsI)[t + 256*it] = yI4[t + 256*it];
    }
#pragma unroll
    for (int it = 0; it < 4; it++)
        reinterpret_cast<float4*>(rws)[t + 256*it] =
            reinterpret_cast<const float4*>(res_w)[t + 256*it];
    if (t < 64) rbs[t] = res_b[t];
    __syncthreads();

    const int og = t & 7, o0 = og*8, pr = t >> 3;     // w0a = pr, w0b = pr + 32
    const ull NEG1 = splat2(-1.f);
    ull C0R[2][4], C2R[2][4], C1R[2][4], C1I[2][4], C3R[2][4], C3I[2][4];
#pragma unroll
    for (int s = 0; s < 2; s++)
#pragma unroll
        for (int j = 0; j < 4; j++) {
            C0R[s][j]=C2R[s][j]=C1R[s][j]=C1I[s][j]=C3R[s][j]=C3I[s][j]=0ull;
        }
    int pa = 0, pb = 0;
    const int stpa = pr, stpb = pr + 32;
#pragma unroll
    for (int kb = 0; kb < 8; kb++) {
        // c = 0
        {
            const int ky = 4*kb;
            ulonglong2 yr0 = *reinterpret_cast<const ulonglong2*>(&YsR[ky*OUTD + o0]);
            ulonglong2 yr1 = *reinterpret_cast<const ulonglong2*>(&YsR[ky*OUTD + o0 + 4]);
            ulonglong2 yi0 = *reinterpret_cast<const ulonglong2*>(&YsI[ky*OUTD + o0]);
            ulonglong2 yi1 = *reinterpret_cast<const ulonglong2*>(&YsI[ky*OUTD + o0 + 4]);
            ulonglong2 tn4 = *reinterpret_cast<const ulonglong2*>(&twn[pa]);
            fma2(C0R[0][0], tn4.x, yr0.x); fma2(C0R[0][0], tn4.y, yi0.x);
            fma2(C0R[0][1], tn4.x, yr0.y); fma2(C0R[0][1], tn4.y, yi0.y);
            fma2(C0R[0][2], tn4.x, yr1.x); fma2(C0R[0][2], tn4.y, yi1.x);
            fma2(C0R[0][3], tn4.x, yr1.y); fma2(C0R[0][3], tn4.y, yi1.y);
            tn4 = *reinterpret_cast<const ulonglong2*>(&twn[pb]);
            fma2(C0R[1][0], tn4.x, yr0.x); fma2(C0R[1][0], tn4.y, yi0.x);
            fma2(C0R[1][1], tn4.x, yr0.y); fma2(C0R[1][1], tn4.y, yi0.y);
            fma2(C0R[1][2], tn4.x, yr1.x); fma2(C0R[1][2], tn4.y, yi1.x);
            fma2(C0R[1][3], tn4.x, yr1.y); fma2(C0R[1][3], tn4.y, yi1.y);
            pa = (pa + stpa) & 255; pb = (pb + stpb) & 255;
        }
        // c = 1
        {
            const int ky = 4*kb + 1;
            ulonglong2 yr0 = *reinterpret_cast<const ulonglong2*>(&YsR[ky*OUTD + o0]);
            ulonglong2 yr1 = *reinterpret_cast<const ulonglong2*>(&YsR[ky*OUTD + o0 + 4]);
            ulonglong2 yi0 = *reinterpret_cast<const ulonglong2*>(&YsI[ky*OUTD + o0]);
            ulonglong2 yi1 = *reinterpret_cast<const ulonglong2*>(&YsI[ky*OUTD + o0 + 4]);
            ulonglong2 tn4 = *reinterpret_cast<const ulonglong2*>(&twn[pa]);
            ulonglong2 tp4 = *reinterpret_cast<const ulonglong2*>(&twp[pa]);
            fma2(C1R[0][0], tn4.x, yr0.x); fma2(C1R[0][0], tn4.y, yi0.x);
            fma2(C1R[0][1], tn4.x, yr0.y); fma2(C1R[0][1], tn4.y, yi0.y);
            fma2(C1R[0][2], tn4.x, yr1.x); fma2(C1R[0][2], tn4.y, yi1.x);
            fma2(C1R[0][3], tn4.x, yr1.y); fma2(C1R[0][3], tn4.y, yi1.y);
            fma2(C1I[0][0], tp4.x, yi0.x); fma2(C1I[0][0], tp4.y, yr0.x);
            fma2(C1I[0][1], tp4.x, yi0.y); fma2(C1I[0][1], tp4.y, yr0.y);
            fma2(C1I[0][2], tp4.x, yi1.x); fma2(C1I[0][2], tp4.y, yr1.x);
            fma2(C1I[0][3], tp4.x, yi1.y); fma2(C1I[0][3], tp4.y, yr1.y);
            tn4 = *reinterpret_cast<const ulonglong2*>(&twn[pb]);
            tp4 = *reinterpret_cast<const ulonglong2*>(&twp[pb]);
            fma2(C1R[1][0], tn4.x, yr0.x); fma2(C1R[1][0], tn4.y, yi0.x);
            fma2(C1R[1][1], tn4.x, yr0.y); fma2(C1R[1][1], tn4.y, yi0.y);
            fma2(C1R[1][2], tn4.x, yr1.x); fma2(C1R[1][2], tn4.y, yi1.x);
            fma2(C1R[1][3], tn4.x, yr1.y); fma2(C1R[1][3], tn4.y, yi1.y);
            fma2(C1I[1][0], tp4.x, yi0.x); fma2(C1I[1][0], tp4.y, yr0.x);
            fma2(C1I[1][1], tp4.x, yi0.y); fma2(C1I[1][1], tp4.y, yr0.y);
            fma2(C1I[1][2], tp4.x, yi1.x); fma2(C1I[1][2], tp4.y, yr1.x);
            fma2(C1I[1][3], tp4.x, yi1.y); fma2(C1I[1][3], tp4.y, yr1.y);
            pa = (pa + stpa) & 255; pb = (pb + stpb) & 255;
        }
        // c = 2
        {
            const int ky = 4*kb + 2;
            ulonglong2 yr0 = *reinterpret_cast<const ulonglong2*>(&YsR[ky*OUTD + o0]);
            ulonglong2 yr1 = *reinterpret_cast<const ulonglong2*>(&YsR[ky*OUTD + o0 + 4]);
            ulonglong2 yi0 = *reinterpret_cast<const ulonglong2*>(&YsI[ky*OUTD + o0]);
            ulonglong2 yi1 = *reinterpret_cast<const ulonglong2*>(&YsI[ky*OUTD + o0 + 4]);
            ulonglong2 tn4 = *reinterpret_cast<const ulonglong2*>(&twn[pa]);
            fma2(C2R[0][0], tn4.x, yr0.x); fma2(C2R[0][0], tn4.y, yi0.x);
            fma2(C2R[0][1], tn4.x, yr0.y); fma2(C2R[0][1], tn4.y, yi0.y);
            fma2(C2R[0][2], tn4.x, yr1.x); fma2(C2R[0][2], tn4.y, yi1.x);
            fma2(C2R[0][3], tn4.x, yr1.y); fma2(C2R[0][3], tn4.y, yi1.y);
            tn4 = *reinterpret_cast<const ulonglong2*>(&twn[pb]);
            fma2(C2R[1][0], tn4.x, yr0.x); fma2(C2R[1][0], tn4.y, yi0.x);
            fma2(C2R[1][1], tn4.x, yr0.y); fma2(C2R[1][1], tn4.y, yi0.y);
            fma2(C2R[1][2], tn4.x, yr1.x); fma2(C2R[1][2], tn4.y, yi1.x);
            fma2(C2R[1][3], tn4.x, yr1.y); fma2(C2R[1][3], tn4.y, yi1.y);
            pa = (pa + stpa) & 255; pb = (pb + stpb) & 255;
        }
        // c = 3
        {
            const int ky = 4*kb + 3;
            ulonglong2 yr0 = *reinterpret_cast<const ulonglong2*>(&YsR[ky*OUTD + o0]);
            ulonglong2 yr1 = *reinterpret_cast<const ulonglong2*>(&YsR[ky*OUTD + o0 + 4]);
            ulonglong2 yi0 = *reinterpret_cast<const ulonglong2*>(&YsI[ky*OUTD + o0]);
            ulonglong2 yi1 = *reinterpret_cast<const ulonglong2*>(&YsI[ky*OUTD + o0 + 4]);
            ulonglong2 tn4 = *reinterpret_cast<const ulonglong2*>(&twn[pa]);
            ulonglong2 tp4 = *reinterpret_cast<const ulonglong2*>(&twp[pa]);
            fma2(C3R[0][0], tn4.x, yr0.x); fma2(C3R[0][0], tn4.y, yi0.x);
            fma2(C3R[0][1], tn4.x, yr0.y); fma2(C3R[0][1], tn4.y, yi0.y);
            fma2(C3R[0][2], tn4.x, yr1.x); fma2(C3R[0][2], tn4.y, yi1.x);
            fma2(C3R[0][3], tn4.x, yr1.y); fma2(C3R[0][3], tn4.y, yi1.y);
            fma2(C3I[0][0], tp4.x, yi0.x); fma2(C3I[0][0], tp4.y, yr0.x);
            fma2(C3I[0][1], tp4.x, yi0.y); fma2(C3I[0][1], tp4.y, yr0.y);
            fma2(C3I[0][2], tp4.x, yi1.x); fma2(C3I[0][2], tp4.y, yr1.x);
            fma2(C3I[0][3], tp4.x, yi1.y); fma2(C3I[0][3], tp4.y, yr1.y);
            tn4 = *reinterpret_cast<const ulonglong2*>(&twn[pb]);
            tp4 = *reinterpret_cast<const ulonglong2*>(&twp[pb]);
            fma2(C3R[1][0], tn4.x, yr0.x); fma2(C3R[1][0], tn4.y, yi0.x);
            fma2(C3R[1][1], tn4.x, yr0.y); fma2(C3R[1][1], tn4.y, yi0.y);
            fma2(C3R[1][2], tn4.x, yr1.x); fma2(C3R[1][2], tn4.y, yi1.x);
            fma2(C3R[1][3], tn4.x, yr1.y); fma2(C3R[1][3], tn4.y, yi1.y);
            fma2(C3I[1][0], tp4.x, yi0.x); fma2(C3I[1][0], tp4.y, yr0.x);
            fma2(C3I[1][1], tp4.x, yi0.y); fma2(C3I[1][1], tp4.y, yr0.y);
            fma2(C3I[1][2], tp4.x, yi1.x); fma2(C3I[1][2], tp4.y, yr1.x);
            fma2(C3I[1][3], tp4.x, yi1.y); fma2(C3I[1][3], tp4.y, yr1.y);
            pa = (pa + stpa) & 255; pb = (pb + stpb) & 255;
        }
    }
    // ---- combine classes into 4 output rows + bias, both w0 ----
    ull ys[2][4][4];
    {
        ulonglong2 b01 = *reinterpret_cast<const ulonglong2*>(&rbs[o0]);
        ulonglong2 b23 = *reinterpret_cast<const ulonglong2*>(&rbs[o0 + 4]);
        ull bias[4] = {b01.x, b01.y, b23.x, b23.y};
#pragma unroll
        for (int s = 0; s < 2; s++)
#pragma unroll
            for (int j = 0; j < 4; j++) {
                ull e  = add2(C0R[s][j], C2R[s][j]);
                ull f  = sub2(C0R[s][j], C2R[s][j], NEG1);
                ull g  = add2(C1R[s][j], C3R[s][j]);
                ull hh = sub2(C3I[s][j], C1I[s][j], NEG1);
                ys[s][0][j] = add2(add2(e, g),  bias[j]);
                ys[s][2][j] = add2(sub2(e, g,  NEG1), bias[j]);
                ys[s][1][j] = add2(add2(f, hh), bias[j]);
                ys[s][3][j] = add2(sub2(f, hh, NEG1), bias[j]);
            }
    }
    // ---- residual GEMM into ys ----
    for (int i = 0; i < IND; i++) {
        ulonglong2 r01 = *reinterpret_cast<const ulonglong2*>(&rws[i*OUTD + o0]);
        ulonglong2 r23 = *reinterpret_cast<const ulonglong2*>(&rws[i*OUTD + o0 + 4]);
#pragma unroll
        for (int s = 0; s < 2; s++) {
            const int wbase = pr + 32*s;
#pragma unroll
            for (int q = 0; q < 4; q++) {
                ull sx = splat2(xs[(wbase + 64*q)*XPAD + i]);
                fma2(ys[s][q][0], sx, r01.x); fma2(ys[s][q][1], sx, r01.y);
                fma2(ys[s][q][2], sx, r23.x); fma2(ys[s][q][3], sx, r23.y);
            }
        }
    }
    // ---- SiLU + store ----
#pragma unroll
    for (int s = 0; s < 2; s++) {
        const int wbase = pr + 32*s;
#pragma unroll
        for (int q = 0; q < 4; q++) {
            float4 v4[2];
#pragma unroll
            for (int c = 0; c < 4; c++) {
                float2 v = unpk(ys[s][q][c]);
                v.x = v.x / (1.f + __expf(-v.x));
                v.y = v.y / (1.f + __expf(-v.y));
                reinterpret_cast<float2*>(v4)[c] = v;
            }
            size_t o = (size_t)((n*RR + h)*RR + (wbase + 64*q))*OUTD + o0;
            *reinterpret_cast<float4*>(&out[o])     = v4[0];
            *reinterpret_cast<float4*>(&out[o + 4]) = v4[1];
        }
    }
}

// ---------------- launch ----------------------------------------------------
extern "C" void kernel_launch(void* const* d_in, const int* in_sizes, int n_in,
                              void* d_out, int out_size) {
    const float* x   = (const float*)d_in[0];
    const float* w0  = (const float*)d_in[1];
    const float* w1  = (const float*)d_in[2];
    const float* rsw = (const float*)d_in[3];
    const float* rsb = (const float*)d_in[4];
    float* out = (float*)d_out;

    cudaFuncSetAttribute(k1_fwd_w, cudaFuncAttributeMaxDynamicSharedMemorySize, 65536);
    cudaFuncSetAttribute(k5_inv_w, cudaFuncAttributeMaxDynamicSharedMemorySize, RR*XPAD*4);

    k_init_tw<<<1, 256>>>();
    k1_fwd_w<<<NB*RR, 256, 65536>>>(x);
    k2_fwd_h<<<NB*MD*2, 256>>>();
    k3_mix<<<KXN*MD, 256>>>(w0, w1);
    k4_inv_h<<<NB*MD*2, 256>>>();
    k5_inv_w<<<NB*RR, 256, RR*XPAD*4>>>(x, rsw, rsb, out);
}

// round 11
// speedup vs baseline: 1.0866x; 1.0404x over previous
#include <cuda_runtime.h>
#include <cuda_fp16.h>

#define NB   8
#define RR   256
#define IND  64
#define OUTD 64
#define MD   32
#define KXN  64

typedef unsigned long long ull;

// ---------------- scratch (device globals; no allocations allowed) ----------
__device__ __half g_XwRh[NB*MD*RR*IND];   // [n][ky][h][i]  forward w-DFT (fp16)
__device__ __half g_XwIh[NB*MD*RR*IND];
__device__ float g_XmR[NB*MD*KXN*IND];    // [ky][kx][n][i] forward modes
__device__ float g_XmI[NB*MD*KXN*IND];
__device__ float g_OmR[NB*MD*KXN*OUTD];   // [n][ky][kx][o] mixed modes
__device__ float g_OmI[NB*MD*KXN*OUTD];
__device__ __half g_Y1Rh[NB*RR*MD*OUTD];  // [n][h][ky][o]  inverse h-DFT (fp16)
__device__ __half g_Y1Ih[NB*RR*MD*OUTD];
__device__ float4 g_tw4p[256];            // (c, c,  s,  s)
__device__ float4 g_tw4n[256];            // (c, c, -s, -s)

// ---------------- packed f32x2 helpers --------------------------------------
__device__ __forceinline__ void fma2(ull &d, ull a, ull b) {
    asm("fma.rn.f32x2 %0, %1, %2, %0;" : "+l"(d) : "l"(a), "l"(b));
}
__device__ __forceinline__ ull splat2(float x) {
    ull r; asm("mov.b64 %0, {%1, %1};" : "=l"(r) : "f"(x)); return r;
}
__device__ __forceinline__ ull pack2(float x, float y) {
    ull r; asm("mov.b64 %0, {%1, %2};" : "=l"(r) : "f"(x), "f"(y)); return r;
}
__device__ __forceinline__ ull mul2(ull a, ull b) {
    ull r; asm("mul.rn.f32x2 %0, %1, %2;" : "=l"(r) : "l"(a), "l"(b)); return r;
}
__device__ __forceinline__ ull add2(ull a, ull b) {
    ull r; asm("add.rn.f32x2 %0, %1, %2;" : "=l"(r) : "l"(a), "l"(b)); return r;
}
__device__ __forceinline__ ull sub2(ull a, ull b, ull negone) {   // a - b
    ull r; asm("fma.rn.f32x2 %0, %1, %2, %3;" : "=l"(r) : "l"(b), "l"(negone), "l"(a)); return r;
}
__device__ __forceinline__ float2 unpk(ull v) {
    float2 r; asm("mov.b64 {%0, %1}, %2;" : "=f"(r.x), "=f"(r.y) : "l"(v)); return r;
}
// ---------------- fp16 pack/unpack helpers ----------------------------------
__device__ __forceinline__ unsigned f22h(float a, float b) {
    __half2 h = __floats2half2_rn(a, b);
    return *reinterpret_cast<unsigned*>(&h);
}
__device__ __forceinline__ ulonglong2 h4f(uint2 u) {            // 4 halves -> 2 packed f32x2
    __half2 ha = *reinterpret_cast<__half2*>(&u.x);
    __half2 hb = *reinterpret_cast<__half2*>(&u.y);
    float2 fa = __half22float2(ha), fb = __half22float2(hb);
    return make_ulonglong2(pack2(fa.x, fa.y), pack2(fb.x, fb.y));
}
__device__ __forceinline__ void h8store(float* dst, uint4 u) {  // 8 halves -> smem f32
    __half2* hp = reinterpret_cast<__half2*>(&u);
    float2 f0 = __half22float2(hp[0]), f1 = __half22float2(hp[1]);
    float2 f2 = __half22float2(hp[2]), f3 = __half22float2(hp[3]);
    *reinterpret_cast<float4*>(dst)     = make_float4(f0.x, f0.y, f1.x, f1.y);
    *reinterpret_cast<float4*>(dst + 4) = make_float4(f2.x, f2.y, f3.x, f3.y);
}

__global__ void k_init_tw() {
    int k = threadIdx.x;
    double a = 6.283185307179586476925286766559 * (double)k / 256.0;
    float c = (float)cos(a), s = (float)sin(a);
    g_tw4p[k] = make_float4(c, c,  s,  s);
    g_tw4n[k] = make_float4(c, c, -s, -s);
}

// ---------------- K1: forward DFT along w (radix-4, 256 thr, 2 ky/thread) ---
__global__ __launch_bounds__(256) void k1_fwd_w(const float* __restrict__ x) {
    extern __shared__ __align__(16) float us[];   // u0|u2|d02|d13, each [64][64]
    __shared__ __align__(16) float4 twp[256], twn[256];
    const int t = threadIdx.x;
    twp[t] = g_tw4p[t]; twn[t] = g_tw4n[t];
    const int b = blockIdx.x, n = b >> 8, h = b & 255;
    const float* xb = x + (size_t)(n*RR + h)*RR*IND;
    float* u0s = us; float* u2s = us + 4096; float* d2s = us + 8192; float* d3s = us + 12288;
#pragma unroll
    for (int it = 0; it < 16; it++) {
        int idx = t + 256*it;                    // idx = w0*64 + i
        float a0 = xb[idx], a1 = xb[idx + 4096], a2 = xb[idx + 8192], a3 = xb[idx + 12288];
        float s02 = a0 + a2, d02 = a0 - a2, s13 = a1 + a3, d13 = a1 - a3;
        u0s[idx] = s02 + s13; u2s[idx] = s02 - s13; d2s[idx] = d02; d3s[idx] = d13;
    }
    __syncthreads();

    const int i0 = (t & 15) * 4;
    const int slot = (t >> 4) & 7;
    const bool oddky = (t >= 128);               // warp-uniform
    const int ky_a = 2*slot + (oddky ? 1 : 0);
    const int ky_b = ky_a + 16;
    ull aR[2][2] = {{0,0},{0,0}}, aI[2][2] = {{0,0},{0,0}};
    int pa = 0, pb = 0;
    const float sc = 1.f/256.f;
    float iscl = sc;

    if (!oddky) {
        const float* Up = (slot & 1) ? u2s : u0s;
        for (int w0 = 0; w0 < 64; w0++) {
            ulonglong2 U = *reinterpret_cast<const ulonglong2*>(&Up[w0*64 + i0]);
            ulonglong2 ta = *reinterpret_cast<const ulonglong2*>(&twn[pa]);
            fma2(aR[0][0], ta.x, U.x); fma2(aR[0][1], ta.x, U.y);
            fma2(aI[0][0], ta.y, U.x); fma2(aI[0][1], ta.y, U.y);
            ulonglong2 tb = *reinterpret_cast<const ulonglong2*>(&twn[pb]);
            fma2(aR[1][0], tb.x, U.x); fma2(aR[1][1], tb.x, U.y);
            fma2(aI[1][0], tb.y, U.x); fma2(aI[1][1], tb.y, U.y);
            pa = (pa + ky_a) & 255; pb = (pb + ky_b) & 255;
        }
    } else {
        const bool c1 = ((slot & 1) == 0);
        const ull S = splat2(c1 ? 1.f : -1.f);
        iscl = c1 ? -sc : sc;
        for (int w0 = 0; w0 < 64; w0++) {
            ulonglong2 D2 = *reinterpret_cast<const ulonglong2*>(&d2s[w0*64 + i0]);
            ulonglong2 D3 = *reinterpret_cast<const ulonglong2*>(&d3s[w0*64 + i0]);
            ull D3r0 = mul2(D3.x, S), D3r1 = mul2(D3.y, S);
            ull D2i0 = mul2(D2.x, S), D2i1 = mul2(D2.y, S);
            ulonglong2 tpa = *reinterpret_cast<const ulonglong2*>(&twp[pa]);
            ulonglong2 tna = *reinterpret_cast<const ulonglong2*>(&twn[pa]);
            fma2(aR[0][0], tpa.x, D2.x); fma2(aR[0][1], tpa.x, D2.y);
            fma2(aR[0][0], tna.y, D3r0); fma2(aR[0][1], tna.y, D3r1);
            fma2(aI[0][0], tpa.x, D3.x); fma2(aI[0][1], tpa.x, D3.y);
            fma2(aI[0][0], tpa.y, D2i0); fma2(aI[0][1], tpa.y, D2i1);
            ulonglong2 tpb = *reinterpret_cast<const ulonglong2*>(&twp[pb]);
            ulonglong2 tnb = *reinterpret_cast<const ulonglong2*>(&twn[pb]);
            fma2(aR[1][0], tpb.x, D2.x); fma2(aR[1][1], tpb.x, D2.y);
            fma2(aR[1][0], tnb.y, D3r0); fma2(aR[1][1], tnb.y, D3r1);
            fma2(aI[1][0], tpb.x, D3.x); fma2(aI[1][1], tpb.x, D3.y);
            fma2(aI[1][0], tpb.y, D2i0); fma2(aI[1][1], tpb.y, D2i1);
            pa = (pa + ky_a) & 255; pb = (pb + ky_b) & 255;
        }
    }
#pragma unroll
    for (int j = 0; j < 2; j++) {
        const int ky = j ? ky_b : ky_a;
        size_t o = (size_t)((n*MD + ky)*RR + h)*IND + i0;
        float2 a0 = unpk(aR[j][0]), a1 = unpk(aR[j][1]);
        *reinterpret_cast<uint2*>(&g_XwRh[o]) =
            make_uint2(f22h(a0.x*sc, a0.y*sc), f22h(a1.x*sc, a1.y*sc));
        a0 = unpk(aI[j][0]); a1 = unpk(aI[j][1]);
        *reinterpret_cast<uint2*>(&g_XwIh[o]) =
            make_uint2(f22h(a0.x*iscl, a0.y*iscl), f22h(a1.x*iscl, a1.y*iscl));
    }
}

// ---------------- K2: forward h-DFT, radix-4, register-prefetch pipeline ----
__global__ __launch_bounds__(256, 3) void k2_fwd_h() {
    __shared__ __align__(16) float Vs[8*16*64];       // 8 planes x [16 h0][64 i] = 32KB
    __shared__ __align__(16) float4 twp[256], twn[256];
    const int t = threadIdx.x;
    twp[t] = g_tw4p[t]; twn[t] = g_tw4n[t];
    const int b = blockIdx.x, half = b & 1, ky = (b >> 1) & 31, n = b >> 6;
    const __half* baseR = g_XwRh + (size_t)(n*MD + ky)*RR*IND;
    const __half* baseI = g_XwIh + (size_t)(n*MD + ky)*RR*IND;
    const int i0 = (t & 15) * 4;
    const int g = t >> 4, c = g & 3, mseg = g >> 2;
    const int kxl0 = 8*mseg + c;                       // slots of class c
    const int kap0 = half ? (224 + kxl0) : kxl0;
    const int kap1 = kap0 + 4;
    const int h0ld = t >> 4, iq = (t & 15) * 4;        // loader role (1 per thread)
    const ull NEG1 = splat2(-1.f);
    ull aR[2][2] = {{0,0},{0,0}}, aI[2][2] = {{0,0},{0,0}};
    int p0 = 0, p1 = 0;

    // prefetch chunk 0 raw rows (fp16) into registers
    uint2 R0u, R1u, R2u, R3u, I0u, I1u, I2u, I3u;
    {
        const __half* pR = baseR + h0ld*IND + iq;
        const __half* pI = baseI + h0ld*IND + iq;
        R0u = *reinterpret_cast<const uint2*>(pR);
        R1u = *reinterpret_cast<const uint2*>(pR + 64*IND);
        R2u = *reinterpret_cast<const uint2*>(pR + 128*IND);
        R3u = *reinterpret_cast<const uint2*>(pR + 192*IND);
        I0u = *reinterpret_cast<const uint2*>(pI);
        I1u = *reinterpret_cast<const uint2*>(pI + 64*IND);
        I2u = *reinterpret_cast<const uint2*>(pI + 128*IND);
        I3u = *reinterpret_cast<const uint2*>(pI + 192*IND);
    }

    for (int hc = 0; hc < 64; hc += 16) {
        __syncthreads();                               // Vs free (prev chunk consumed)
        {   // convert + butterfly registers -> Vs
            ulonglong2 R0 = h4f(R0u), R1 = h4f(R1u), R2 = h4f(R2u), R3 = h4f(R3u);
            ulonglong2 I0 = h4f(I0u), I1 = h4f(I1u), I2 = h4f(I2u), I3 = h4f(I3u);
            ull sRx = add2(R0.x, R2.x), sRy = add2(R0.y, R2.y);
            ull dRx = sub2(R0.x, R2.x, NEG1), dRy = sub2(R0.y, R2.y, NEG1);
            ull uRx = add2(R1.x, R3.x), uRy = add2(R1.y, R3.y);
            ull eRx = sub2(R1.x, R3.x, NEG1), eRy = sub2(R1.y, R3.y, NEG1);
            ull sIx = add2(I0.x, I2.x), sIy = add2(I0.y, I2.y);
            ull dIx = sub2(I0.x, I2.x, NEG1), dIy = sub2(I0.y, I2.y, NEG1);
            ull uIx = add2(I1.x, I3.x), uIy = add2(I1.y, I3.y);
            ull eIx = sub2(I1.x, I3.x, NEG1), eIy = sub2(I1.y, I3.y, NEG1);
            const int rb = h0ld*64 + iq;
            ulonglong2* vp;
            vp = reinterpret_cast<ulonglong2*>(&Vs[0*1024 + rb]);   // V0R
            *vp = make_ulonglong2(add2(sRx, uRx), add2(sRy, uRy));
            vp = reinterpret_cast<ulonglong2*>(&Vs[1*1024 + rb]);   // V0I
            *vp = make_ulonglong2(add2(sIx, uIx), add2(sIy, uIy));
            vp = reinterpret_cast<ulonglong2*>(&Vs[2*1024 + rb]);   // V1R = dR + eI
            *vp = make_ulonglong2(add2(dRx, eIx), add2(dRy, eIy));
            vp = reinterpret_cast<ulonglong2*>(&Vs[3*1024 + rb]);   // V1I = dI - eR
            *vp = make_ulonglong2(sub2(dIx, eRx, NEG1), sub2(dIy, eRy, NEG1));
            vp = reinterpret_cast<ulonglong2*>(&Vs[4*1024 + rb]);   // V2R
            *vp = make_ulonglong2(sub2(sRx, uRx, NEG1), sub2(sRy, uRy, NEG1));
            vp = reinterpret_cast<ulonglong2*>(&Vs[5*1024 + rb]);   // V2I
            *vp = make_ulonglong2(sub2(sIx, uIx, NEG1), sub2(sIy, uIy, NEG1));
            vp = reinterpret_cast<ulonglong2*>(&Vs[6*1024 + rb]);   // V3R = dR - eI
            *vp = make_ulonglong2(sub2(dRx, eIx, NEG1), sub2(dRy, eIy, NEG1));
            vp = reinterpret_cast<ulonglong2*>(&Vs[7*1024 + rb]);   // V3I = dI + eR
            *vp = make_ulonglong2(add2(dIx, eRx), add2(dIy, eRy));
        }
        __syncthreads();                               // Vs ready
        if (hc < 48) {                                 // prefetch next chunk
            const __half* pR = baseR + (hc + 16 + h0ld)*IND + iq;
            const __half* pI = baseI + (hc + 16 + h0ld)*IND + iq;
            R0u = *reinterpret_cast<const uint2*>(pR);
            R1u = *reinterpret_cast<const uint2*>(pR + 64*IND);
            R2u = *reinterpret_cast<const uint2*>(pR + 128*IND);
            R3u = *reinterpret_cast<const uint2*>(pR + 192*IND);
            I0u = *reinterpret_cast<const uint2*>(pI);
            I1u = *reinterpret_cast<const uint2*>(pI + 64*IND);
            I2u = *reinterpret_cast<const uint2*>(pI + 128*IND);
            I3u = *reinterpret_cast<const uint2*>(pI + 192*IND);
        }
        const float* VRb = &Vs[(c*2 + 0)*1024];
        const float* VIb = &Vs[(c*2 + 1)*1024];
        for (int h0l = 0; h0l < 16; h0l++) {
            ulonglong2 VR = *reinterpret_cast<const ulonglong2*>(&VRb[h0l*64 + i0]);
            ulonglong2 VI = *reinterpret_cast<const ulonglong2*>(&VIb[h0l*64 + i0]);
            ulonglong2 tp4 = *reinterpret_cast<const ulonglong2*>(&twp[p0]);
            ulonglong2 tn4 = *reinterpret_cast<const ulonglong2*>(&twn[p0]);
            fma2(aR[0][0], tp4.x, VR.x); fma2(aR[0][0], tp4.y, VI.x);
            fma2(aR[0][1], tp4.x, VR.y); fma2(aR[0][1], tp4.y, VI.y);
            fma2(aI[0][0], tp4.x, VI.x); fma2(aI[0][0], tn4.y, VR.x);
            fma2(aI[0][1], tp4.x, VI.y); fma2(aI[0][1], tn4.y, VR.y);
            p0 = (p0 + kap0) & 255;
            tp4 = *reinterpret_cast<const ulonglong2*>(&twp[p1]);
            tn4 = *reinterpret_cast<const ulonglong2*>(&twn[p1]);
            fma2(aR[1][0], tp4.x, VR.x); fma2(aR[1][0], tp4.y, VI.x);
            fma2(aR[1][1], tp4.x, VR.y); fma2(aR[1][1], tp4.y, VI.y);
            fma2(aI[1][0], tp4.x, VI.x); fma2(aI[1][0], tn4.y, VR.x);
            fma2(aI[1][1], tp4.x, VI.y); fma2(aI[1][1], tn4.y, VR.y);
            p1 = (p1 + kap1) & 255;
        }
    }
#pragma unroll
    for (int j = 0; j < 2; j++) {
        int kxs = half*32 + kxl0 + 4*j;
        size_t o = (size_t)((ky*KXN + kxs)*NB + n)*IND + i0;
        float2 a0 = unpk(aR[j][0]), a1 = unpk(aR[j][1]);
        *reinterpret_cast<float4*>(&g_XmR[o]) = make_float4(a0.x, a0.y, a1.x, a1.y);
        a0 = unpk(aI[j][0]); a1 = unpk(aI[j][1]);
        *reinterpret_cast<float4*>(&g_XmI[o]) = make_float4(a0.x, a0.y, a1.x, a1.y);
    }
}

// ---------------- K3: per-mode complex channel mix (8x64x64) ----------------
// o-pair per thread; weights via LDG.128 (2 complex), Xm interleaved broadcast.
__global__ __launch_bounds__(256) void k3_mix(const float* __restrict__ w0,
                                              const float* __restrict__ w1) {
    __shared__ float Xs2[NB*IND*2];                   // interleaved (R,I)
    const int t = threadIdx.x, b = blockIdx.x;
    const int kx = b >> 5, ky = b & 31;
    size_t xb = (size_t)(ky*KXN + kx)*NB*IND;
#pragma unroll
    for (int it = 0; it < 2; it++) {
        int idx = t + 256*it;
        Xs2[2*idx]     = g_XmR[xb + idx];
        Xs2[2*idx + 1] = g_XmI[xb + idx];
    }
    __syncthreads();
    const float4* wp4 = reinterpret_cast<const float4*>(
        (kx < MD) ? (w0 + (size_t)(kx*MD + ky)*IND*OUTD*2)
                  : (w1 + (size_t)((kx - MD)*MD + ky)*IND*OUTD*2));
    const int o2 = t & 31, n = t >> 5;                // o0 = 2*o2, one n per thread
    float r0 = 0.f, i0 = 0.f, r1 = 0.f, i1 = 0.f;
#pragma unroll 8
    for (int i = 0; i < IND; i++) {
        float4 w = wp4[i*32 + o2];                    // (wR0,wI0,wR1,wI1)
        float2 xv = *reinterpret_cast<const float2*>(&Xs2[(n*IND + i)*2]);
        r0 = fmaf(xv.x, w.x, fmaf(-xv.y, w.y, r0));
        i0 = fmaf(xv.x, w.y, fmaf( xv.y, w.x, i0));
        r1 = fmaf(xv.x, w.z, fmaf(-xv.y, w.w, r1));
        i1 = fmaf(xv.x, w.w, fmaf( xv.y, w.z, i1));
    }
    size_t gg = (size_t)((n*MD + ky)*KXN + kx)*OUTD + 2*o2;
    *reinterpret_cast<float2*>(&g_OmR[gg]) = make_float2(r0, r1);
    *reinterpret_cast<float2*>(&g_OmI[gg]) = make_float2(i0, i1);
}

// ---------------- K4: inverse h-DFT, radix-4 on output ----------------------
#define K4STEP(CR, CI) { \
    ulonglong2 R0 = *reinterpret_cast<const ulonglong2*>(&sR[kxo]); \
    ulonglong2 R1 = *reinterpret_cast<const ulonglong2*>(&sR[kxo + 4]); \
    ulonglong2 I0 = *reinterpret_cast<const ulonglong2*>(&sI[kxo]); \
    ulonglong2 I1 = *reinterpret_cast<const ulonglong2*>(&sI[kxo + 4]); \
    ulonglong2 tp4 = *reinterpret_cast<const ulonglong2*>(&twp[p]); \
    ulonglong2 tn4 = *reinterpret_cast<const ulonglong2*>(&twn[p]); \
    fma2(CR[0], tn4.x, R0.x); fma2(CR[0], tn4.y, I0.x); \
    fma2(CR[1], tn4.x, R0.y); fma2(CR[1], tn4.y, I0.y); \
    fma2(CR[2], tn4.x, R1.x); fma2(CR[2], tn4.y, I1.x); \
    fma2(CR[3], tn4.x, R1.y); fma2(CR[3], tn4.y, I1.y); \
    fma2(CI[0], tp4.x, I0.x); fma2(CI[0], tp4.y, R0.x); \
    fma2(CI[1], tp4.x, I0.y); fma2(CI[1], tp4.y, R0.y); \
    fma2(CI[2], tp4.x, I1.x); fma2(CI[2], tp4.y, R1.x); \
    fma2(CI[3], tp4.x, I1.y); fma2(CI[3], tp4.y, R1.y); \
    p = (p + h0) & 255; kxo += OUTD; }

__global__ __launch_bounds__(256) void k4_inv_h() {
    __shared__ __align__(16) float sR[KXN*OUTD], sI[KXN*OUTD];
    __shared__ __align__(16) float4 twp[256], twn[256];
    const int t = threadIdx.x;
    twp[t] = g_tw4p[t]; twn[t] = g_tw4n[t];
    const int b = blockIdx.x, grp = b & 1, ky = (b >> 1) & 31, n = b >> 6;
    const float4* pR = reinterpret_cast<const float4*>(g_OmR + (size_t)(n*MD + ky)*KXN*OUTD);
    const float4* pI = reinterpret_cast<const float4*>(g_OmI + (size_t)(n*MD + ky)*KXN*OUTD);
#pragma unroll
    for (int it = 0; it < 4; it++) {
        reinterpret_cast<float4*>(sR)[t + 256*it] = pR[t + 256*it];
        reinterpret_cast<float4*>(sI)[t + 256*it] = pI[t + 256*it];
    }
    __syncthreads();
    const int o0 = (t & 7) * 8, h0 = grp*32 + (t >> 3);
    ull C0R[4], C0I[4], C1R[4], C1I[4], C2R[4], C2I[4], C3R[4], C3I[4];
#pragma unroll
    for (int j = 0; j < 4; j++) {
        C0R[j]=C0I[j]=C1R[j]=C1I[j]=0ull;
        C2R[j]=C2I[j]=C3R[j]=C3I[j]=0ull;
    }
#pragma unroll 1
    for (int kh = 0; kh < 2; kh++) {
        int p = kh ? ((224*h0) & 255) : 0;
        int kxo = (kh*32)*OUTD + o0;
#pragma unroll
        for (int kk = 0; kk < 32; kk += 4) {
            K4STEP(C0R, C0I)
            K4STEP(C1R, C1I)
            K4STEP(C2R, C2I)
            K4STEP(C3R, C3I)
        }
    }
    const ull NEG1 = splat2(-1.f);
    const ull FAC2 = splat2((ky == 0 ? 1.f : 2.f) * (1.f/256.f));
    const size_t obase = (size_t)((n*RR + h0)*MD + ky)*OUTD + o0;
#pragma unroll
    for (int j = 0; j < 4; j++) {
        ull ER = add2(C0R[j], C2R[j]), EI = add2(C0I[j], C2I[j]);
        ull FR = sub2(C0R[j], C2R[j], NEG1), FI = sub2(C0I[j], C2I[j], NEG1);
        ull GR = add2(C1R[j], C3R[j]), GI = add2(C1I[j], C3I[j]);
        ull HR = sub2(C1R[j], C3R[j], NEG1), HI = sub2(C1I[j], C3I[j], NEG1);
        ull YR[4] = { add2(ER, GR), sub2(FR, HI, NEG1), sub2(ER, GR, NEG1), add2(FR, HI) };
        ull YI[4] = { add2(EI, GI), add2(FI, HR), sub2(EI, GI, NEG1), sub2(FI, HR, NEG1) };
#pragma unroll
        for (int q = 0; q < 4; q++) {
            size_t o = obase + (size_t)(64*q)*MD*OUTD + 2*j;
            float2 vr = unpk(mul2(YR[q], FAC2));
            float2 vi = unpk(mul2(YI[q], FAC2));
            *reinterpret_cast<unsigned*>(&g_Y1Rh[o]) = f22h(vr.x, vr.y);
            *reinterpret_cast<unsigned*>(&g_Y1Ih[o]) = f22h(vi.x, vi.y);
        }
    }
}

// ---------------- K5: radix-4 inverse w synthesis + residual + SiLU ---------
#define XPAD 68
__global__ __launch_bounds__(256) void k5_inv_w(const float* __restrict__ x,
                                                const float* __restrict__ res_w,
                                                const float* __restrict__ res_b,
                                                float* __restrict__ out) {
    extern __shared__ __align__(16) float xs[];       // [256][XPAD]
    __shared__ __align__(16) float YsR[MD*OUTD], YsI[MD*OUTD];
    __shared__ __align__(16) float rws[IND*OUTD];
    __shared__ __align__(16) float4 twp[256], twn[256];
    __shared__ __align__(16) float rbs[64];
    const int t = threadIdx.x, b = blockIdx.x, n = b >> 8, h = b & 255;
    twp[t] = g_tw4p[t];
    twn[t] = g_tw4n[t];
    const float4* xp = reinterpret_cast<const float4*>(x + (size_t)(n*RR + h)*RR*IND);
#pragma unroll
    for (int it = 0; it < 16; it++) {
        int j = t + 256*it;
        float4 v = xp[j];
        int w = j >> 4, c = j & 15;
        *reinterpret_cast<float4*>(&xs[w*XPAD + c*4]) = v;
    }
    {   // Y1 fp16 -> fp32 smem (one uint4 = 8 halves per thread per plane)
        const uint4* yRu = reinterpret_cast<const uint4*>(g_Y1Rh + (size_t)(n*RR + h)*MD*OUTD);
        const uint4* yIu = reinterpret_cast<const uint4*>(g_Y1Ih + (size_t)(n*RR + h)*MD*OUTD);
        h8store(&YsR[t*8], yRu[t]);
        h8store(&YsI[t*8], yIu[t]);
    }
#pragma unroll
    for (int it = 0; it < 4; it++)
        reinterpret_cast<float4*>(rws)[t + 256*it] =
            reinterpret_cast<const float4*>(res_w)[t + 256*it];
    if (t < 64) rbs[t] = res_b[t];
    __syncthreads();

    const int og = t & 7, o0 = og*8, pr = t >> 3;     // w0a = pr, w0b = pr + 32
    const ull NEG1 = splat2(-1.f);
    ull C0R[2][4], C2R[2][4], C1R[2][4], C1I[2][4], C3R[2][4], C3I[2][4];
#pragma unroll
    for (int s = 0; s < 2; s++)
#pragma unroll
        for (int j = 0; j < 4; j++) {
            C0R[s][j]=C2R[s][j]=C1R[s][j]=C1I[s][j]=C3R[s][j]=C3I[s][j]=0ull;
        }
    int pa = 0, pb = 0;
    const int stpa = pr, stpb = pr + 32;
#pragma unroll
    for (int kb = 0; kb < 8; kb++) {
        // c = 0
        {
            const int ky = 4*kb;
            ulonglong2 yr0 = *reinterpret_cast<const ulonglong2*>(&YsR[ky*OUTD + o0]);
            ulonglong2 yr1 = *reinterpret_cast<const ulonglong2*>(&YsR[ky*OUTD + o0 + 4]);
            ulonglong2 yi0 = *reinterpret_cast<const ulonglong2*>(&YsI[ky*OUTD + o0]);
            ulonglong2 yi1 = *reinterpret_cast<const ulonglong2*>(&YsI[ky*OUTD + o0 + 4]);
            ulonglong2 tn4 = *reinterpret_cast<const ulonglong2*>(&twn[pa]);
            fma2(C0R[0][0], tn4.x, yr0.x); fma2(C0R[0][0], tn4.y, yi0.x);
            fma2(C0R[0][1], tn4.x, yr0.y); fma2(C0R[0][1], tn4.y, yi0.y);
            fma2(C0R[0][2], tn4.x, yr1.x); fma2(C0R[0][2], tn4.y, yi1.x);
            fma2(C0R[0][3], tn4.x, yr1.y); fma2(C0R[0][3], tn4.y, yi1.y);
            tn4 = *reinterpret_cast<const ulonglong2*>(&twn[pb]);
            fma2(C0R[1][0], tn4.x, yr0.x); fma2(C0R[1][0], tn4.y, yi0.x);
            fma2(C0R[1][1], tn4.x, yr0.y); fma2(C0R[1][1], tn4.y, yi0.y);
            fma2(C0R[1][2], tn4.x, yr1.x); fma2(C0R[1][2], tn4.y, yi1.x);
            fma2(C0R[1][3], tn4.x, yr1.y); fma2(C0R[1][3], tn4.y, yi1.y);
            pa = (pa + stpa) & 255; pb = (pb + stpb) & 255;
        }
        // c = 1
        {
            const int ky = 4*kb + 1;
            ulonglong2 yr0 = *reinterpret_cast<const ulonglong2*>(&YsR[ky*OUTD + o0]);
            ulonglong2 yr1 = *reinterpret_cast<const ulonglong2*>(&YsR[ky*OUTD + o0 + 4]);
            ulonglong2 yi0 = *reinterpret_cast<const ulonglong2*>(&YsI[ky*OUTD + o0]);
            ulonglong2 yi1 = *reinterpret_cast<const ulonglong2*>(&YsI[ky*OUTD + o0 + 4]);
            ulonglong2 tn4 = *reinterpret_cast<const ulonglong2*>(&twn[pa]);
            ulonglong2 tp4 = *reinterpret_cast<const ulonglong2*>(&twp[pa]);
            fma2(C1R[0][0], tn4.x, yr0.x); fma2(C1R[0][0], tn4.y, yi0.x);
            fma2(C1R[0][1], tn4.x, yr0.y); fma2(C1R[0][1], tn4.y, yi0.y);
            fma2(C1R[0][2], tn4.x, yr1.x); fma2(C1R[0][2], tn4.y, yi1.x);
            fma2(C1R[0][3], tn4.x, yr1.y); fma2(C1R[0][3], tn4.y, yi1.y);
            fma2(C1I[0][0], tp4.x, yi0.x); fma2(C1I[0][0], tp4.y, yr0.x);
            fma2(C1I[0][1], tp4.x, yi0.y); fma2(C1I[0][1], tp4.y, yr0.y);
            fma2(C1I[0][2], tp4.x, yi1.x); fma2(C1I[0][2], tp4.y, yr1.x);
            fma2(C1I[0][3], tp4.x, yi1.y); fma2(C1I[0][3], tp4.y, yr1.y);
            tn4 = *reinterpret_cast<const ulonglong2*>(&twn[pb]);
            tp4 = *reinterpret_cast<const ulonglong2*>(&twp[pb]);
            fma2(C1R[1][0], tn4.x, yr0.x); fma2(C1R[1][0], tn4.y, yi0.x);
            fma2(C1R[1][1], tn4.x, yr0.y); fma2(C1R[1][1], tn4.y, yi0.y);
            fma2(C1R[1][2], tn4.x, yr1.x); fma2(C1R[1][2], tn4.y, yi1.x);
            fma2(C1R[1][3], tn4.x, yr1.y); fma2(C1R[1][3], tn4.y, yi1.y);
            fma2(C1I[1][0], tp4.x, yi0.x); fma2(C1I[1][0], tp4.y, yr0.x);
            fma2(C1I[1][1], tp4.x, yi0.y); fma2(C1I[1][1], tp4.y, yr0.y);
            fma2(C1I[1][2], tp4.x, yi1.x); fma2(C1I[1][2], tp4.y, yr1.x);
            fma2(C1I[1][3], tp4.x, yi1.y); fma2(C1I[1][3], tp4.y, yr1.y);
            pa = (pa + stpa) & 255; pb = (pb + stpb) & 255;
        }
        // c = 2
        {
            const int ky = 4*kb + 2;
            ulonglong2 yr0 = *reinterpret_cast<const ulonglong2*>(&YsR[ky*OUTD + o0]);
            ulonglong2 yr1 = *reinterpret_cast<const ulonglong2*>(&YsR[ky*OUTD + o0 + 4]);
            ulonglong2 yi0 = *reinterpret_cast<const ulonglong2*>(&YsI[ky*OUTD + o0]);
            ulonglong2 yi1 = *reinterpret_cast<const ulonglong2*>(&YsI[ky*OUTD + o0 + 4]);
            ulonglong2 tn4 = *reinterpret_cast<const ulonglong2*>(&twn[pa]);
            fma2(C2R[0][0], tn4.x, yr0.x); fma2(C2R[0][0], tn4.y, yi0.x);
            fma2(C2R[0][1], tn4.x, yr0.y); fma2(C2R[0][1], tn4.y, yi0.y);
            fma2(C2R[0][2], tn4.x, yr1.x); fma2(C2R[0][2], tn4.y, yi1.x);
            fma2(C2R[0][3], tn4.x, yr1.y); fma2(C2R[0][3], tn4.y, yi1.y);
            tn4 = *reinterpret_cast<const ulonglong2*>(&twn[pb]);
            fma2(C2R[1][0], tn4.x, yr0.x); fma2(C2R[1][0], tn4.y, yi0.x);
            fma2(C2R[1][1], tn4.x, yr0.y); fma2(C2R[1][1], tn4.y, yi0.y);
            fma2(C2R[1][2], tn4.x, yr1.x); fma2(C2R[1][2], tn4.y, yi1.x);
            fma2(C2R[1][3], tn4.x, yr1.y); fma2(C2R[1][3], tn4.y, yi1.y);
            pa = (pa + stpa) & 255; pb = (pb + stpb) & 255;
        }
        // c = 3
        {
            const int ky = 4*kb + 3;
            ulonglong2 yr0 = *reinterpret_cast<const ulonglong2*>(&YsR[ky*OUTD + o0]);
            ulonglong2 yr1 = *reinterpret_cast<const ulonglong2*>(&YsR[ky*OUTD + o0 + 4]);
            ulonglong2 yi0 = *reinterpret_cast<const ulonglong2*>(&YsI[ky*OUTD + o0]);
            ulonglong2 yi1 = *reinterpret_cast<const ulonglong2*>(&YsI[ky*OUTD + o0 + 4]);
            ulonglong2 tn4 = *reinterpret_cast<const ulonglong2*>(&twn[pa]);
            ulonglong2 tp4 = *reinterpret_cast<const ulonglong2*>(&twp[pa]);
            fma2(C3R[0][0], tn4.x, yr0.x); fma2(C3R[0][0], tn4.y, yi0.x);
            fma2(C3R[0][1], tn4.x, yr0.y); fma2(C3R[0][1], tn4.y, yi0.y);
            fma2(C3R[0][2], tn4.x, yr1.x); fma2(C3R[0][2], tn4.y, yi1.x);
            fma2(C3R[0][3], tn4.x, yr1.y); fma2(C3R[0][3], tn4.y, yi1.y);
            fma2(C3I[0][0], tp4.x, yi0.x); fma2(C3I[0][0], tp4.y, yr0.x);
            fma2(C3I[0][1], tp4.x, yi0.y); fma2(C3I[0][1], tp4.y, yr0.y);
            fma2(C3I[0][2], tp4.x, yi1.x); fma2(C3I[0][2], tp4.y, yr1.x);
            fma2(C3I[0][3], tp4.x, yi1.y); fma2(C3I[0][3], tp4.y, yr1.y);
            tn4 = *reinterpret_cast<const ulonglong2*>(&twn[pb]);
            tp4 = *reinterpret_cast<const ulonglong2*>(&twp[pb]);
            fma2(C3R[1][0], tn4.x, yr0.x); fma2(C3R[1][0], tn4.y, yi0.x);
            fma2(C3R[1][1], tn4.x, yr0.y); fma2(C3R[1][1], tn4.y, yi0.y);
            fma2(C3R[1][2], tn4.x, yr1.x); fma2(C3R[1][2], tn4.y, yi1.x);
            fma2(C3R[1][3], tn4.x, yr1.y); fma2(C3R[1][3], tn4.y, yi1.y);
            fma2(C3I[1][0], tp4.x, yi0.x); fma2(C3I[1][0], tp4.y, yr0.x);
            fma2(C3I[1][1], tp4.x, yi0.y); fma2(C3I[1][1], tp4.y, yr0.y);
            fma2(C3I[1][2], tp4.x, yi1.x); fma2(C3I[1][2], tp4.y, yr1.x);
            fma2(C3I[1][3], tp4.x, yi1.y); fma2(C3I[1][3], tp4.y, yr1.y);
            pa = (pa + stpa) & 255; pb = (pb + stpb) & 255;
        }
    }
    // ---- combine classes into 4 output rows + bias, both w0 ----
    ull ys[2][4][4];
    {
        ulonglong2 b01 = *reinterpret_cast<const ulonglong2*>(&rbs[o0]);
        ulonglong2 b23 = *reinterpret_cast<const ulonglong2*>(&rbs[o0 + 4]);
        ull bias[4] = {b01.x, b01.y, b23.x, b23.y};
#pragma unroll
        for (int s = 0; s < 2; s++)
#pragma unroll
            for (int j = 0; j < 4; j++) {
                ull e  = add2(C0R[s][j], C2R[s][j]);
                ull f  = sub2(C0R[s][j], C2R[s][j], NEG1);
                ull g  = add2(C1R[s][j], C3R[s][j]);
                ull hh = sub2(C3I[s][j], C1I[s][j], NEG1);
                ys[s][0][j] = add2(add2(e, g),  bias[j]);
                ys[s][2][j] = add2(sub2(e, g,  NEG1), bias[j]);
                ys[s][1][j] = add2(add2(f, hh), bias[j]);
                ys[s][3][j] = add2(sub2(f, hh, NEG1), bias[j]);
            }
    }
    // ---- residual GEMM into ys ----
    for (int i = 0; i < IND; i++) {
        ulonglong2 r01 = *reinterpret_cast<const ulonglong2*>(&rws[i*OUTD + o0]);
        ulonglong2 r23 = *reinterpret_cast<const ulonglong2*>(&rws[i*OUTD + o0 + 4]);
#pragma unroll
        for (int s = 0; s < 2; s++) {
            const int wbase = pr + 32*s;
#pragma unroll
            for (int q = 0; q < 4; q++) {
                ull sx = splat2(xs[(wbase + 64*q)*XPAD + i]);
                fma2(ys[s][q][0], sx, r01.x); fma2(ys[s][q][1], sx, r01.y);
                fma2(ys[s][q][2], sx, r23.x); fma2(ys[s][q][3], sx, r23.y);
            }
        }
    }
    // ---- SiLU + store ----
#pragma unroll
    for (int s = 0; s < 2; s++) {
        const int wbase = pr + 32*s;
#pragma unroll
        for (int q = 0; q < 4; q++) {
            float4 v4[2];
#pragma unroll
            for (int c = 0; c < 4; c++) {
                float2 v = unpk(ys[s][q][c]);
                v.x = v.x / (1.f + __expf(-v.x));
                v.y = v.y / (1.f + __expf(-v.y));
                reinterpret_cast<float2*>(v4)[c] = v;
            }
            size_t o = (size_t)((n*RR + h)*RR + (wbase + 64*q))*OUTD + o0;
            *reinterpret_cast<float4*>(&out[o])     = v4[0];
            *reinterpret_cast<float4*>(&out[o + 4]) = v4[1];
        }
    }
}

// ---------------- launch ----------------------------------------------------
extern "C" void kernel_launch(void* const* d_in, const int* in_sizes, int n_in,
                              void* d_out, int out_size) {
    const float* x   = (const float*)d_in[0];
    const float* w0  = (const float*)d_in[1];
    const float* w1  = (const float*)d_in[2];
    const float* rsw = (const float*)d_in[3];
    const float* rsb = (const float*)d_in[4];
    float* out = (float*)d_out;

    cudaFuncSetAttribute(k1_fwd_w, cudaFuncAttributeMaxDynamicSharedMemorySize, 65536);
    cudaFuncSetAttribute(k5_inv_w, cudaFuncAttributeMaxDynamicSharedMemorySize, RR*XPAD*4);

    k_init_tw<<<1, 256>>>();
    k1_fwd_w<<<NB*RR, 256, 65536>>>(x);
    k2_fwd_h<<<NB*MD*2, 256>>>();
    k3_mix<<<KXN*MD, 256>>>(w0, w1);
    k4_inv_h<<<NB*MD*2, 256>>>();
    k5_inv_w<<<NB*RR, 256, RR*XPAD*4>>>(x, rsw, rsb, out);
}